// round 8
// baseline (speedup 1.0000x reference)
#include <cuda_runtime.h>
#include <cuda_bf16.h>
#include <cstdint>

#define DM     1024
#define NHEADS 16
#define HD     64
#define BATCH  2
#define SEQ    1024
#define LCACHE 1024
#define TTOT   2048
#define BH     (BATCH * NHEADS)   // 32
#define MROWS  (BATCH * SEQ)      // 2048

// ---------------------------------------------------------------------------
// Scratch (device globals; no allocation allowed)
// ---------------------------------------------------------------------------
__device__ __nv_bfloat16 g_xhi[MROWS * DM], g_xlo[MROWS * DM];
__device__ __nv_bfloat16 g_whi[4 * DM * DM], g_wlo[4 * DM * DM];
__device__ __nv_bfloat16 g_qhi[BH * SEQ * HD],  g_qlo[BH * SEQ * HD];
__device__ __nv_bfloat16 g_khi[BH * TTOT * HD], g_klo[BH * TTOT * HD];
__device__ __nv_bfloat16 g_vhi[BH * TTOT * HD], g_vlo[BH * TTOT * HD];
__device__ __nv_bfloat16 g_ahi[MROWS * DM], g_alo[MROWS * DM];

// ---------------------------------------------------------------------------
// PTX helpers — baseline ISA only (compute_103-safe)
// ---------------------------------------------------------------------------
__device__ __forceinline__ uint32_t smem_u32(const void* p) {
    uint32_t a;
    asm("{ .reg .u64 t; cvta.to.shared.u64 t, %1; cvt.u32.u64 %0, t; }"
        : "=r"(a) : "l"(p));
    return a;
}
__device__ __forceinline__ void cp16(uint32_t d, const void* s) {
    asm volatile("cp.async.cg.shared.global [%0], [%1], 16;" :: "r"(d), "l"(s) : "memory");
}
__device__ __forceinline__ void cp_commit() {
    asm volatile("cp.async.commit_group;" ::: "memory");
}
template <int N> __device__ __forceinline__ void cp_wait() {
    asm volatile("cp.async.wait_group %0;" :: "n"(N) : "memory");
}
__device__ __forceinline__ void ldmx4(uint32_t* r, uint32_t a) {
    asm volatile("ldmatrix.sync.aligned.m8n8.x4.shared.b16 {%0,%1,%2,%3}, [%4];"
        : "=r"(r[0]), "=r"(r[1]), "=r"(r[2]), "=r"(r[3]) : "r"(a));
}
__device__ __forceinline__ void ldmx4t(uint32_t* r, uint32_t a) {
    asm volatile("ldmatrix.sync.aligned.m8n8.x4.trans.shared.b16 {%0,%1,%2,%3}, [%4];"
        : "=r"(r[0]), "=r"(r[1]), "=r"(r[2]), "=r"(r[3]) : "r"(a));
}
__device__ __forceinline__ void ldmx2(uint32_t* r, uint32_t a) {
    asm volatile("ldmatrix.sync.aligned.m8n8.x2.shared.b16 {%0,%1}, [%2];"
        : "=r"(r[0]), "=r"(r[1]) : "r"(a));
}
__device__ __forceinline__ void mma16816(float* d, const uint32_t* a, const uint32_t* b) {
    asm volatile(
        "mma.sync.aligned.m16n8k16.row.col.f32.bf16.bf16.f32 "
        "{%0,%1,%2,%3}, {%4,%5,%6,%7}, {%8,%9}, {%0,%1,%2,%3};"
        : "+f"(d[0]), "+f"(d[1]), "+f"(d[2]), "+f"(d[3])
        : "r"(a[0]), "r"(a[1]), "r"(a[2]), "r"(a[3]), "r"(b[0]), "r"(b[1]));
}
__device__ __forceinline__ float ex2f(float x) {
    float y;
    asm("ex2.approx.f32 %0, %1;" : "=f"(y) : "f"(x));
    return y;
}
__device__ __forceinline__ uint32_t pack_hi(float a, float b, __nv_bfloat16& ha, __nv_bfloat16& hb) {
    ha = __float2bfloat16_rn(a);
    hb = __float2bfloat16_rn(b);
    __nv_bfloat162 t = __halves2bfloat162(ha, hb);
    return *(uint32_t*)&t;
}

// ---------------------------------------------------------------------------
// hi/lo split kernels
// ---------------------------------------------------------------------------
__global__ void split_kernel(const float* __restrict__ in,
                             __nv_bfloat16* __restrict__ hi,
                             __nv_bfloat16* __restrict__ lo, int n4)
{
    int i = blockIdx.x * blockDim.x + threadIdx.x;
    if (i >= n4) return;
    float4 v = ((const float4*)in)[i];
    __nv_bfloat16 h0 = __float2bfloat16_rn(v.x);
    __nv_bfloat16 h1 = __float2bfloat16_rn(v.y);
    __nv_bfloat16 h2 = __float2bfloat16_rn(v.z);
    __nv_bfloat16 h3 = __float2bfloat16_rn(v.w);
    __nv_bfloat16 l0 = __float2bfloat16_rn(v.x - __bfloat162float(h0));
    __nv_bfloat16 l1 = __float2bfloat16_rn(v.y - __bfloat162float(h1));
    __nv_bfloat16 l2 = __float2bfloat16_rn(v.z - __bfloat162float(h2));
    __nv_bfloat16 l3 = __float2bfloat16_rn(v.w - __bfloat162float(h3));
    ((__nv_bfloat162*)hi)[2 * i]     = __halves2bfloat162(h0, h1);
    ((__nv_bfloat162*)hi)[2 * i + 1] = __halves2bfloat162(h2, h3);
    ((__nv_bfloat162*)lo)[2 * i]     = __halves2bfloat162(l0, l1);
    ((__nv_bfloat162*)lo)[2 * i + 1] = __halves2bfloat162(l2, l3);
}

__global__ void split_w4(const float* __restrict__ w0, const float* __restrict__ w1,
                         const float* __restrict__ w2, const float* __restrict__ w3,
                         __nv_bfloat16* __restrict__ hi, __nv_bfloat16* __restrict__ lo)
{
    int p = blockIdx.y;
    const float* src = (p == 0) ? w0 : (p == 1) ? w1 : (p == 2) ? w2 : w3;
    size_t off2 = (size_t)p * (DM * DM / 2);
    int i = blockIdx.x * blockDim.x + threadIdx.x;
    float4 v = ((const float4*)src)[i];
    __nv_bfloat16 h0 = __float2bfloat16_rn(v.x);
    __nv_bfloat16 h1 = __float2bfloat16_rn(v.y);
    __nv_bfloat16 h2 = __float2bfloat16_rn(v.z);
    __nv_bfloat16 h3 = __float2bfloat16_rn(v.w);
    __nv_bfloat16 l0 = __float2bfloat16_rn(v.x - __bfloat162float(h0));
    __nv_bfloat16 l1 = __float2bfloat16_rn(v.y - __bfloat162float(h1));
    __nv_bfloat16 l2 = __float2bfloat16_rn(v.z - __bfloat162float(h2));
    __nv_bfloat16 l3 = __float2bfloat16_rn(v.w - __bfloat162float(h3));
    ((__nv_bfloat162*)hi)[off2 + 2 * i]     = __halves2bfloat162(h0, h1);
    ((__nv_bfloat162*)hi)[off2 + 2 * i + 1] = __halves2bfloat162(h2, h3);
    ((__nv_bfloat162*)lo)[off2 + 2 * i]     = __halves2bfloat162(l0, l1);
    ((__nv_bfloat162*)lo)[off2 + 2 * i + 1] = __halves2bfloat162(l2, l3);
}

// Convert fp32 KV cache -> bf16 hi/lo planes at t < LCACHE of [bh][TTOT][64]
__global__ void convert_cache(const float* __restrict__ ck, const float* __restrict__ cv)
{
    const int which = blockIdx.y;
    const float* src = which ? cv : ck;
    __nv_bfloat16* hi = which ? g_vhi : g_khi;
    __nv_bfloat16* lo = which ? g_vlo : g_klo;
    int i = blockIdx.x * blockDim.x + threadIdx.x;
    float4 v = ((const float4*)src)[i];
    int el = i * 4;
    int bh = el >> 16;
    int rest = el & 65535;
    size_t o = (size_t)bh * (TTOT * HD) + rest;
    __nv_bfloat16 h0 = __float2bfloat16_rn(v.x);
    __nv_bfloat16 h1 = __float2bfloat16_rn(v.y);
    __nv_bfloat16 h2 = __float2bfloat16_rn(v.z);
    __nv_bfloat16 h3 = __float2bfloat16_rn(v.w);
    __nv_bfloat16 l0 = __float2bfloat16_rn(v.x - __bfloat162float(h0));
    __nv_bfloat16 l1 = __float2bfloat16_rn(v.y - __bfloat162float(h1));
    __nv_bfloat16 l2 = __float2bfloat16_rn(v.z - __bfloat162float(h2));
    __nv_bfloat16 l3 = __float2bfloat16_rn(v.w - __bfloat162float(h3));
    *(__nv_bfloat162*)(hi + o)     = __halves2bfloat162(h0, h1);
    *(__nv_bfloat162*)(hi + o + 2) = __halves2bfloat162(h2, h3);
    *(__nv_bfloat162*)(lo + o)     = __halves2bfloat162(l0, l1);
    *(__nv_bfloat162*)(lo + o + 2) = __halves2bfloat162(l2, l3);
}

// ---------------------------------------------------------------------------
// Warp-MMA bf16 GEMM (hi/lo 3-term). 512 threads, 16 warps, warp tile 32x32.
// CTA 128x128, BK=32, 3-stage cp.async pipeline.
// ---------------------------------------------------------------------------
#define ST       3
#define CHUNKS   32
#define ROWPAD   80
#define PLANE_B  (128 * ROWPAD)
#define STAGE_B  (4 * PLANE_B)
#define GSMEM    (ST * STAGE_B)

__global__ __launch_bounds__(512, 1)
void gemm_mma(const __nv_bfloat16* __restrict__ Ahi, const __nv_bfloat16* __restrict__ Alo,
              const __nv_bfloat16* __restrict__ Whi, const __nv_bfloat16* __restrict__ Wlo,
              const float* __restrict__ b0, const float* __restrict__ b1, const float* __restrict__ b2,
              __nv_bfloat16* __restrict__ ph0, __nv_bfloat16* __restrict__ pl0,
              __nv_bfloat16* __restrict__ ph1, __nv_bfloat16* __restrict__ pl1,
              __nv_bfloat16* __restrict__ ph2, __nv_bfloat16* __restrict__ pl2,
              float* __restrict__ fout, int headwise)
{
    extern __shared__ char smem[];
    const uint32_t sb = smem_u32(smem);
    const int tid = threadIdx.x, wid = tid >> 5, lane = tid & 31;
    const int n0 = blockIdx.x * 128, m0 = blockIdx.y * 128, z = blockIdx.z;
    const __nv_bfloat16* Wh = Whi + (size_t)z * DM * DM;
    const __nv_bfloat16* Wl = Wlo + (size_t)z * DM * DM;
    const float* bias = (z == 0) ? b0 : (z == 1) ? b1 : b2;

    const int wm = wid & 3;       // 4 m-blocks of 32
    const int wn = wid >> 2;      // 4 n-blocks of 32

    auto load_chunk = [&](int stage, int koff) {
        const uint32_t base = sb + stage * STAGE_B;
#pragma unroll
        for (int it = 0; it < 4; it++) {
            int g = it * 512 + tid;            // 0..2047 granules of 16B
            int plane = g >> 9;
            int row = (g >> 2) & 127;
            int c = g & 3;
            uint32_t dst = base + plane * PLANE_B + row * ROWPAD + c * 16;
            const __nv_bfloat16* src;
            if (plane == 0)      src = Ahi + (size_t)(m0 + row) * DM + koff + c * 8;
            else if (plane == 1) src = Alo + (size_t)(m0 + row) * DM + koff + c * 8;
            else if (plane == 2) src = Wh  + (size_t)(n0 + row) * DM + koff + c * 8;
            else                 src = Wl  + (size_t)(n0 + row) * DM + koff + c * 8;
            cp16(dst, src);
        }
        cp_commit();
    };

    load_chunk(0, 0);
    load_chunk(1, 32);

    float acc[2][4][4];
#pragma unroll
    for (int i = 0; i < 2; i++)
#pragma unroll
        for (int j = 0; j < 4; j++)
#pragma unroll
            for (int r = 0; r < 4; r++) acc[i][j][r] = 0.f;

    const int lr16 = lane & 15, lc16 = lane >> 4;
    const int br8 = lane & 7, bc8 = (lane >> 3) & 1;

    for (int i = 0; i < CHUNKS; i++) {
        if (i + 2 < CHUNKS) load_chunk((i + 2) % ST, (i + 2) * 32);
        else cp_commit();
        cp_wait<2>();
        __syncthreads();

        const uint32_t stb = sb + (i % ST) * STAGE_B;
#pragma unroll
        for (int ks = 0; ks < 2; ks++) {
            uint32_t ah[2][4], al[2][4];
#pragma unroll
            for (int mi = 0; mi < 2; mi++) {
                uint32_t ad = stb + (wm * 32 + mi * 16 + lr16) * ROWPAD + ks * 32 + lc16 * 16;
                ldmx4(ah[mi], ad);
                ldmx4(al[mi], ad + PLANE_B);
            }
            uint32_t bh[4][2], bl[4][2];
#pragma unroll
            for (int nj = 0; nj < 4; nj++) {
                uint32_t bd = stb + 2 * PLANE_B + (wn * 32 + nj * 8 + br8) * ROWPAD + ks * 32 + bc8 * 16;
                ldmx2(bh[nj], bd);
                ldmx2(bl[nj], bd + PLANE_B);
            }
#pragma unroll
            for (int mi = 0; mi < 2; mi++)
#pragma unroll
                for (int nj = 0; nj < 4; nj++) {
                    mma16816(acc[mi][nj], ah[mi], bh[nj]);
                    mma16816(acc[mi][nj], ah[mi], bl[nj]);
                    mma16816(acc[mi][nj], al[mi], bh[nj]);
                }
        }
        __syncthreads();
    }

    // epilogue
    __nv_bfloat16* ph = (z == 0) ? ph0 : (z == 1) ? ph1 : ph2;
    __nv_bfloat16* pl = (z == 0) ? pl0 : (z == 1) ? pl1 : pl2;
    const int tstr = (z == 0) ? SEQ : TTOT;
    const int toff = (z == 0) ? 0 : LCACHE;

#pragma unroll
    for (int nj = 0; nj < 4; nj++) {
        const int n = n0 + wn * 32 + nj * 8 + (lane & 3) * 2;
        const float bx = bias[n], by = bias[n + 1];
        const int h = n >> 6, d = n & 63;
#pragma unroll
        for (int mi = 0; mi < 2; mi++) {
#pragma unroll
            for (int half = 0; half < 2; half++) {
                const int m = m0 + wm * 32 + mi * 16 + (lane >> 2) + half * 8;
                float vx = acc[mi][nj][half * 2] + bx;
                float vy = acc[mi][nj][half * 2 + 1] + by;
                if (headwise) {
                    int b = m >> 10, s = m & 1023;
                    size_t ad = (((size_t)b * NHEADS + h) * tstr + toff + s) * HD + d;
                    __nv_bfloat16 hx = __float2bfloat16_rn(vx);
                    __nv_bfloat16 hy = __float2bfloat16_rn(vy);
                    *(__nv_bfloat162*)(ph + ad) = __halves2bfloat162(hx, hy);
                    *(__nv_bfloat162*)(pl + ad) = __halves2bfloat162(
                        __float2bfloat16_rn(vx - __bfloat162float(hx)),
                        __float2bfloat16_rn(vy - __bfloat162float(hy)));
                } else {
                    *(float2*)&fout[(size_t)m * DM + n] = make_float2(vx, vy);
                }
            }
        }
    }
}

// ---------------------------------------------------------------------------
// Tensor-core flash attention (unchanged from R7).
// ---------------------------------------------------------------------------
#define ASTRIDE 144
#define APLANE  (64 * ASTRIDE)
#define AKVOFF  (2 * APLANE)
#define ASMEM   (2 * APLANE + 2 * 4 * APLANE)
#define SCLOG2  0.18033688011112042f

__global__ __launch_bounds__(128, 2)
void attn_tc()
{
    extern __shared__ char smem[];
    const uint32_t sb = smem_u32(smem);
    const int tid = threadIdx.x, w = tid >> 5, lane = tid & 31;
    const int bh = blockIdx.x;
    const int qt = 15 - blockIdx.y;
    const int q0 = qt * 64;
    const int nt = qt + 17;

#pragma unroll
    for (int it = 0; it < 8; it++) {
        int g = it * 128 + tid;
        int plane = g >> 9, row = (g >> 3) & 63, gc = g & 7;
        const __nv_bfloat16* src = (plane ? g_qlo : g_qhi)
            + ((size_t)bh * SEQ + q0 + row) * HD + gc * 8;
        cp16(sb + plane * APLANE + row * ASTRIDE + gc * 16, src);
    }
    cp_commit();

    auto load_kv = [&](int kt, int st) {
        uint32_t base = sb + AKVOFF + st * (4 * APLANE);
        int t0 = kt * 64;
#pragma unroll
        for (int it = 0; it < 16; it++) {
            int g = it * 128 + tid;
            int plane = g >> 9, row = (g >> 3) & 63, gc = g & 7;
            size_t off = ((size_t)bh * TTOT + t0 + row) * HD + gc * 8;
            const __nv_bfloat16* src;
            if (plane == 0)      src = g_khi + off;
            else if (plane == 1) src = g_klo + off;
            else if (plane == 2) src = g_vhi + off;
            else                 src = g_vlo + off;
            cp16(base + plane * APLANE + row * ASTRIDE + gc * 16, src);
        }
        cp_commit();
    };
    load_kv(0, 0);
    cp_wait<0>();
    __syncthreads();

    uint32_t qh[4][4], ql[4][4];
#pragma unroll
    for (int kc = 0; kc < 4; kc++) {
        uint32_t qa = sb + (w * 16 + (lane & 15)) * ASTRIDE + kc * 32 + (lane >> 4) * 16;
        ldmx4(qh[kc], qa);
        ldmx4(ql[kc], qa + APLANE);
    }

    float oacc[8][4];
#pragma unroll
    for (int i = 0; i < 8; i++)
#pragma unroll
        for (int j = 0; j < 4; j++) oacc[i][j] = 0.f;
    float mrow[2] = {-1e30f, -1e30f}, lrow[2] = {0.f, 0.f};

    for (int kt = 0; kt < nt; kt++) {
        const int st = kt & 1;
        if (kt + 1 < nt) load_kv(kt + 1, st ^ 1);
        const uint32_t kbase = sb + AKVOFF + st * (4 * APLANE);
        const uint32_t vbase = kbase + 2 * APLANE;

        float sacc[8][4];
#pragma unroll
        for (int nb = 0; nb < 8; nb++) {
#pragma unroll
            for (int j = 0; j < 4; j++) sacc[nb][j] = 0.f;
        }
#pragma unroll
        for (int nb = 0; nb < 8; nb++) {
            uint32_t kh[8], kl[8];
            uint32_t ka = kbase + (nb * 8 + (lane & 7)) * ASTRIDE + (lane >> 3) * 16;
            ldmx4(kh, ka);  ldmx4(kh + 4, ka + 64);
            ldmx4(kl, ka + APLANE);  ldmx4(kl + 4, ka + APLANE + 64);
#pragma unroll
            for (int kc = 0; kc < 4; kc++) {
                mma16816(sacc[nb], qh[kc], &kh[kc * 2]);
                mma16816(sacc[nb], qh[kc], &kl[kc * 2]);
                mma16816(sacc[nb], ql[kc], &kh[kc * 2]);
            }
        }

        if (kt == nt - 1) {
            const int qloc = w * 16 + (lane >> 2);
#pragma unroll
            for (int nb = 0; nb < 8; nb++) {
#pragma unroll
                for (int c = 0; c < 4; c++) {
                    int tl = nb * 8 + (lane & 3) * 2 + (c & 1);
                    int qr = qloc + (c >> 1) * 8;
                    if (tl > qr) sacc[nb][c] = -1e30f;
                }
            }
        }

        uint32_t phf[4][4], plf[4][4];
#pragma unroll
        for (int i = 0; i < 2; i++) {
            float mx = -1e30f;
#pragma unroll
            for (int nb = 0; nb < 8; nb++)
                mx = fmaxf(mx, fmaxf(sacc[nb][2 * i], sacc[nb][2 * i + 1]));
            mx = fmaxf(mx, __shfl_xor_sync(0xffffffffu, mx, 1));
            mx = fmaxf(mx, __shfl_xor_sync(0xffffffffu, mx, 2));
            float mn = fmaxf(mrow[i], mx);
            float f = ex2f((mrow[i] - mn) * SCLOG2);
            mrow[i] = mn;
            float sum = 0.f;
#pragma unroll
            for (int nb = 0; nb < 8; nb++) {
                float p0 = ex2f((sacc[nb][2 * i] - mn) * SCLOG2);
                float p1 = ex2f((sacc[nb][2 * i + 1] - mn) * SCLOG2);
                sacc[nb][2 * i] = p0;
                sacc[nb][2 * i + 1] = p1;
                sum += p0 + p1;
            }
            sum += __shfl_xor_sync(0xffffffffu, sum, 1);
            sum += __shfl_xor_sync(0xffffffffu, sum, 2);
            lrow[i] = lrow[i] * f + sum;
#pragma unroll
            for (int nbd = 0; nbd < 8; nbd++) {
                oacc[nbd][2 * i] *= f;
                oacc[nbd][2 * i + 1] *= f;
            }
        }

#pragma unroll
        for (int kc = 0; kc < 4; kc++) {
#pragma unroll
            for (int q = 0; q < 4; q++) {
                int nb = 2 * kc + (q >> 1);
                float a = sacc[nb][(q & 1) * 2];
                float b = sacc[nb][(q & 1) * 2 + 1];
                __nv_bfloat16 ha, hb2;
                phf[kc][q] = pack_hi(a, b, ha, hb2);
                __nv_bfloat162 lo2 = __halves2bfloat162(
                    __float2bfloat16_rn(a - __bfloat162float(ha)),
                    __float2bfloat16_rn(b - __bfloat162float(hb2)));
                plf[kc][q] = *(uint32_t*)&lo2;
            }
        }

#pragma unroll
        for (int kc = 0; kc < 4; kc++) {
#pragma unroll
            for (int dp = 0; dp < 4; dp++) {
                uint32_t vh[4], vl[4];
                uint32_t va = vbase + (kc * 16 + ((lane >> 3) & 1) * 8 + (lane & 7)) * ASTRIDE
                            + (dp * 16 + (lane >> 4) * 8) * 2;
                ldmx4t(vh, va);
                ldmx4t(vl, va + APLANE);
                mma16816(oacc[dp * 2],     phf[kc], &vh[0]);
                mma16816(oacc[dp * 2],     phf[kc], &vl[0]);
                mma16816(oacc[dp * 2],     plf[kc], &vh[0]);
                mma16816(oacc[dp * 2 + 1], phf[kc], &vh[2]);
                mma16816(oacc[dp * 2 + 1], phf[kc], &vl[2]);
                mma16816(oacc[dp * 2 + 1], plf[kc], &vh[2]);
            }
        }

        cp_wait<0>();
        __syncthreads();
    }

    const int b = bh >> 4, h = bh & 15;
#pragma unroll
    for (int i = 0; i < 2; i++) {
        float inv = 1.f / lrow[i];
        int srow = q0 + w * 16 + (lane >> 2) + i * 8;
        size_t mbase = ((size_t)b * SEQ + srow) * DM + h * HD + (lane & 3) * 2;
#pragma unroll
        for (int nbd = 0; nbd < 8; nbd++) {
            float v0 = oacc[nbd][2 * i] * inv;
            float v1 = oacc[nbd][2 * i + 1] * inv;
            __nv_bfloat16 h0 = __float2bfloat16_rn(v0);
            __nv_bfloat16 h1 = __float2bfloat16_rn(v1);
            *(__nv_bfloat162*)(g_ahi + mbase + nbd * 8) = __halves2bfloat162(h0, h1);
            *(__nv_bfloat162*)(g_alo + mbase + nbd * 8) = __halves2bfloat162(
                __float2bfloat16_rn(v0 - __bfloat162float(h0)),
                __float2bfloat16_rn(v1 - __bfloat162float(h1)));
        }
    }
}

// ---------------------------------------------------------------------------
// launch
// ---------------------------------------------------------------------------
extern "C" void kernel_launch(void* const* d_in, const int* in_sizes, int n_in,
                              void* d_out, int out_size)
{
    const float* x  = (const float*)d_in[0];
    const float* ck = (const float*)d_in[1];
    const float* cv = (const float*)d_in[2];
    const float* Wq = (const float*)d_in[3];
    const float* bq = (const float*)d_in[4];
    const float* Wk = (const float*)d_in[5];
    const float* bk = (const float*)d_in[6];
    const float* Wv = (const float*)d_in[7];
    const float* bv = (const float*)d_in[8];
    const float* Wo = (const float*)d_in[9];
    const float* bo = (const float*)d_in[10];
    float* out = (float*)d_out;

    __nv_bfloat16 *xhi, *xlo, *whi, *wlo, *ahi, *alo;
    __nv_bfloat16 *qhi, *qlo, *khi, *klo, *vhi, *vlo;
    cudaGetSymbolAddress((void**)&xhi, g_xhi);
    cudaGetSymbolAddress((void**)&xlo, g_xlo);
    cudaGetSymbolAddress((void**)&whi, g_whi);
    cudaGetSymbolAddress((void**)&wlo, g_wlo);
    cudaGetSymbolAddress((void**)&ahi, g_ahi);
    cudaGetSymbolAddress((void**)&alo, g_alo);
    cudaGetSymbolAddress((void**)&qhi, g_qhi);
    cudaGetSymbolAddress((void**)&qlo, g_qlo);
    cudaGetSymbolAddress((void**)&khi, g_khi);
    cudaGetSymbolAddress((void**)&klo, g_klo);
    cudaGetSymbolAddress((void**)&vhi, g_vhi);
    cudaGetSymbolAddress((void**)&vlo, g_vlo);

    cudaFuncSetAttribute(gemm_mma, cudaFuncAttributeMaxDynamicSharedMemorySize, GSMEM);
    cudaFuncSetAttribute(attn_tc, cudaFuncAttributeMaxDynamicSharedMemorySize, ASMEM);

    // 1) splits + cache conversion
    split_kernel<<<(MROWS * DM / 4 + 255) / 256, 256>>>(x, xhi, xlo, MROWS * DM / 4);
    split_w4<<<dim3(DM * DM / 4 / 256, 4), 256>>>(Wq, Wk, Wv, Wo, whi, wlo);
    convert_cache<<<dim3(BH * LCACHE * HD / 4 / 256, 2), 256>>>(ck, cv);

    // 2) QKV projections -> bf16 hi/lo Q/K/V planes
    gemm_mma<<<dim3(8, 16, 3), 512, GSMEM>>>(xhi, xlo, whi, wlo,
                                             bq, bk, bv,
                                             qhi, qlo, khi, klo, vhi, vlo,
                                             nullptr, 1);

    // 3) tensor-core flash attention -> bf16 hi/lo planes
    attn_tc<<<dim3(BH, 16), 128, ASMEM>>>();

    // 4) output projection -> fp32 d_out
    gemm_mma<<<dim3(8, 16, 1), 512, GSMEM>>>(ahi, alo,
                                             whi + (size_t)3 * DM * DM, wlo + (size_t)3 * DM * DM,
                                             bo, bo, bo,
                                             nullptr, nullptr, nullptr, nullptr, nullptr, nullptr,
                                             out, 0);
}

// round 10
// speedup vs baseline: 1.1369x; 1.1369x over previous
#include <cuda_runtime.h>
#include <cuda_bf16.h>
#include <cstdint>

#define DM     1024
#define NHEADS 16
#define HD     64
#define BATCH  2
#define SEQ    1024
#define LCACHE 1024
#define TTOT   2048
#define BH     (BATCH * NHEADS)   // 32
#define MROWS  (BATCH * SEQ)      // 2048

// ---------------------------------------------------------------------------
// Scratch (device globals; no allocation allowed)
// ---------------------------------------------------------------------------
__device__ __nv_bfloat16 g_xhi[MROWS * DM], g_xlo[MROWS * DM];
__device__ __nv_bfloat16 g_whi[4 * DM * DM], g_wlo[4 * DM * DM];
__device__ __nv_bfloat16 g_qhi[BH * SEQ * HD],  g_qlo[BH * SEQ * HD];
__device__ __nv_bfloat16 g_khi[BH * TTOT * HD], g_klo[BH * TTOT * HD];
__device__ __nv_bfloat16 g_vhi[BH * TTOT * HD], g_vlo[BH * TTOT * HD];
__device__ __nv_bfloat16 g_ahi[MROWS * DM], g_alo[MROWS * DM];

// ---------------------------------------------------------------------------
// PTX helpers — baseline ISA only (compute_103-safe)
// ---------------------------------------------------------------------------
__device__ __forceinline__ uint32_t smem_u32(const void* p) {
    uint32_t a;
    asm("{ .reg .u64 t; cvta.to.shared.u64 t, %1; cvt.u32.u64 %0, t; }"
        : "=r"(a) : "l"(p));
    return a;
}
__device__ __forceinline__ void cp16(uint32_t d, const void* s) {
    asm volatile("cp.async.cg.shared.global [%0], [%1], 16;" :: "r"(d), "l"(s) : "memory");
}
__device__ __forceinline__ void cp_commit() {
    asm volatile("cp.async.commit_group;" ::: "memory");
}
template <int N> __device__ __forceinline__ void cp_wait() {
    asm volatile("cp.async.wait_group %0;" :: "n"(N) : "memory");
}
__device__ __forceinline__ void ldmx4(uint32_t* r, uint32_t a) {
    asm volatile("ldmatrix.sync.aligned.m8n8.x4.shared.b16 {%0,%1,%2,%3}, [%4];"
        : "=r"(r[0]), "=r"(r[1]), "=r"(r[2]), "=r"(r[3]) : "r"(a));
}
__device__ __forceinline__ void ldmx4t(uint32_t* r, uint32_t a) {
    asm volatile("ldmatrix.sync.aligned.m8n8.x4.trans.shared.b16 {%0,%1,%2,%3}, [%4];"
        : "=r"(r[0]), "=r"(r[1]), "=r"(r[2]), "=r"(r[3]) : "r"(a));
}
__device__ __forceinline__ void mma16816(float* d, const uint32_t* a, const uint32_t* b) {
    asm volatile(
        "mma.sync.aligned.m16n8k16.row.col.f32.bf16.bf16.f32 "
        "{%0,%1,%2,%3}, {%4,%5,%6,%7}, {%8,%9}, {%0,%1,%2,%3};"
        : "+f"(d[0]), "+f"(d[1]), "+f"(d[2]), "+f"(d[3])
        : "r"(a[0]), "r"(a[1]), "r"(a[2]), "r"(a[3]), "r"(b[0]), "r"(b[1]));
}
__device__ __forceinline__ float ex2f(float x) {
    float y;
    asm("ex2.approx.f32 %0, %1;" : "=f"(y) : "f"(x));
    return y;
}
__device__ __forceinline__ uint32_t pack_hi(float a, float b, __nv_bfloat16& ha, __nv_bfloat16& hb) {
    ha = __float2bfloat16_rn(a);
    hb = __float2bfloat16_rn(b);
    __nv_bfloat162 t = __halves2bfloat162(ha, hb);
    return *(uint32_t*)&t;
}

// ---------------------------------------------------------------------------
// hi/lo split kernels
// ---------------------------------------------------------------------------
__global__ void split_kernel(const float* __restrict__ in,
                             __nv_bfloat16* __restrict__ hi,
                             __nv_bfloat16* __restrict__ lo, int n4)
{
    int i = blockIdx.x * blockDim.x + threadIdx.x;
    if (i >= n4) return;
    float4 v = ((const float4*)in)[i];
    __nv_bfloat16 h0 = __float2bfloat16_rn(v.x);
    __nv_bfloat16 h1 = __float2bfloat16_rn(v.y);
    __nv_bfloat16 h2 = __float2bfloat16_rn(v.z);
    __nv_bfloat16 h3 = __float2bfloat16_rn(v.w);
    __nv_bfloat16 l0 = __float2bfloat16_rn(v.x - __bfloat162float(h0));
    __nv_bfloat16 l1 = __float2bfloat16_rn(v.y - __bfloat162float(h1));
    __nv_bfloat16 l2 = __float2bfloat16_rn(v.z - __bfloat162float(h2));
    __nv_bfloat16 l3 = __float2bfloat16_rn(v.w - __bfloat162float(h3));
    ((__nv_bfloat162*)hi)[2 * i]     = __halves2bfloat162(h0, h1);
    ((__nv_bfloat162*)hi)[2 * i + 1] = __halves2bfloat162(h2, h3);
    ((__nv_bfloat162*)lo)[2 * i]     = __halves2bfloat162(l0, l1);
    ((__nv_bfloat162*)lo)[2 * i + 1] = __halves2bfloat162(l2, l3);
}

__global__ void split_w4(const float* __restrict__ w0, const float* __restrict__ w1,
                         const float* __restrict__ w2, const float* __restrict__ w3,
                         __nv_bfloat16* __restrict__ hi, __nv_bfloat16* __restrict__ lo)
{
    int p = blockIdx.y;
    const float* src = (p == 0) ? w0 : (p == 1) ? w1 : (p == 2) ? w2 : w3;
    size_t off2 = (size_t)p * (DM * DM / 2);
    int i = blockIdx.x * blockDim.x + threadIdx.x;
    float4 v = ((const float4*)src)[i];
    __nv_bfloat16 h0 = __float2bfloat16_rn(v.x);
    __nv_bfloat16 h1 = __float2bfloat16_rn(v.y);
    __nv_bfloat16 h2 = __float2bfloat16_rn(v.z);
    __nv_bfloat16 h3 = __float2bfloat16_rn(v.w);
    __nv_bfloat16 l0 = __float2bfloat16_rn(v.x - __bfloat162float(h0));
    __nv_bfloat16 l1 = __float2bfloat16_rn(v.y - __bfloat162float(h1));
    __nv_bfloat16 l2 = __float2bfloat16_rn(v.z - __bfloat162float(h2));
    __nv_bfloat16 l3 = __float2bfloat16_rn(v.w - __bfloat162float(h3));
    ((__nv_bfloat162*)hi)[off2 + 2 * i]     = __halves2bfloat162(h0, h1);
    ((__nv_bfloat162*)hi)[off2 + 2 * i + 1] = __halves2bfloat162(h2, h3);
    ((__nv_bfloat162*)lo)[off2 + 2 * i]     = __halves2bfloat162(l0, l1);
    ((__nv_bfloat162*)lo)[off2 + 2 * i + 1] = __halves2bfloat162(l2, l3);
}

// Convert fp32 KV cache -> bf16 hi/lo planes at t < LCACHE of [bh][TTOT][64]
__global__ void convert_cache(const float* __restrict__ ck, const float* __restrict__ cv)
{
    const int which = blockIdx.y;
    const float* src = which ? cv : ck;
    __nv_bfloat16* hi = which ? g_vhi : g_khi;
    __nv_bfloat16* lo = which ? g_vlo : g_klo;
    int i = blockIdx.x * blockDim.x + threadIdx.x;
    float4 v = ((const float4*)src)[i];
    int el = i * 4;
    int bh = el >> 16;
    int rest = el & 65535;
    size_t o = (size_t)bh * (TTOT * HD) + rest;
    __nv_bfloat16 h0 = __float2bfloat16_rn(v.x);
    __nv_bfloat16 h1 = __float2bfloat16_rn(v.y);
    __nv_bfloat16 h2 = __float2bfloat16_rn(v.z);
    __nv_bfloat16 h3 = __float2bfloat16_rn(v.w);
    __nv_bfloat16 l0 = __float2bfloat16_rn(v.x - __bfloat162float(h0));
    __nv_bfloat16 l1 = __float2bfloat16_rn(v.y - __bfloat162float(h1));
    __nv_bfloat16 l2 = __float2bfloat16_rn(v.z - __bfloat162float(h2));
    __nv_bfloat16 l3 = __float2bfloat16_rn(v.w - __bfloat162float(h3));
    *(__nv_bfloat162*)(hi + o)     = __halves2bfloat162(h0, h1);
    *(__nv_bfloat162*)(hi + o + 2) = __halves2bfloat162(h2, h3);
    *(__nv_bfloat162*)(lo + o)     = __halves2bfloat162(l0, l1);
    *(__nv_bfloat162*)(lo + o + 2) = __halves2bfloat162(l2, l3);
}

// ---------------------------------------------------------------------------
// Warp-MMA bf16 GEMM (hi/lo 3-term). 256 threads, 8 warps, warp tile 64x32.
// CTA 128x128, BK=64, 2-stage cp.async pipeline (one full chunk of overlap).
// Rows padded to 144B (128B data + 16B) -> conflict-free ldmatrix phases.
// ---------------------------------------------------------------------------
#define ST       2
#define CHUNKS   16
#define ROWB     144
#define PLANE_B  (128 * ROWB)    // 18432
#define STAGE_B  (4 * PLANE_B)   // 73728
#define GSMEM    (ST * STAGE_B)  // 147456

__global__ __launch_bounds__(256, 1)
void gemm_mma(const __nv_bfloat16* __restrict__ Ahi, const __nv_bfloat16* __restrict__ Alo,
              const __nv_bfloat16* __restrict__ Whi, const __nv_bfloat16* __restrict__ Wlo,
              const float* __restrict__ b0, const float* __restrict__ b1, const float* __restrict__ b2,
              __nv_bfloat16* __restrict__ ph0, __nv_bfloat16* __restrict__ pl0,
              __nv_bfloat16* __restrict__ ph1, __nv_bfloat16* __restrict__ pl1,
              __nv_bfloat16* __restrict__ ph2, __nv_bfloat16* __restrict__ pl2,
              float* __restrict__ fout, int headwise)
{
    extern __shared__ char smem[];
    const uint32_t sb = smem_u32(smem);
    const int tid = threadIdx.x, wid = tid >> 5, lane = tid & 31;
    const int n0 = blockIdx.x * 128, m0 = blockIdx.y * 128, z = blockIdx.z;
    const __nv_bfloat16* Wh = Whi + (size_t)z * DM * DM;
    const __nv_bfloat16* Wl = Wlo + (size_t)z * DM * DM;
    const float* bias = (z == 0) ? b0 : (z == 1) ? b1 : b2;

    const int wm = wid & 1;       // 2 m-blocks of 64
    const int wn = wid >> 1;      // 4 n-blocks of 32

    // chunk loader: 4 planes x 128 rows x 128B (BK=64 bf16), rows padded 144B
    auto load_chunk = [&](int stage, int koff) {
        const uint32_t base = sb + stage * STAGE_B;
#pragma unroll
        for (int it = 0; it < 16; it++) {
            int g = it * 256 + tid;            // 0..4095 granules of 16B
            int plane = g >> 10;               // 1024 granules per plane
            int row = (g >> 3) & 127;
            int gc = g & 7;
            uint32_t dst = base + plane * PLANE_B + row * ROWB + gc * 16;
            const __nv_bfloat16* src;
            if (plane == 0)      src = Ahi + (size_t)(m0 + row) * DM + koff + gc * 8;
            else if (plane == 1) src = Alo + (size_t)(m0 + row) * DM + koff + gc * 8;
            else if (plane == 2) src = Wh  + (size_t)(n0 + row) * DM + koff + gc * 8;
            else                 src = Wl  + (size_t)(n0 + row) * DM + koff + gc * 8;
            cp16(dst, src);
        }
        cp_commit();
    };

    load_chunk(0, 0);

    float acc[4][4][4];
#pragma unroll
    for (int i = 0; i < 4; i++)
#pragma unroll
        for (int j = 0; j < 4; j++)
#pragma unroll
            for (int r = 0; r < 4; r++) acc[i][j][r] = 0.f;

    const int lr16 = lane & 15, lc16 = lane >> 4;
    // B ldmx4 lane mapping: 4 groups of 8 lanes -> (njp row block, k-half)
    const int brow = ((lane >> 4) & 1) * 8 + (lane & 7);   // row within 16-row pair
    const int bcol = ((lane >> 3) & 1) * 16;               // k-half byte offset

    for (int i = 0; i < CHUNKS; i++) {
        if (i + 1 < CHUNKS) { load_chunk((i + 1) & 1, (i + 1) * 64); cp_wait<1>(); }
        else                { cp_wait<0>(); }
        __syncthreads();

        const uint32_t stb = sb + (i & 1) * STAGE_B;
#pragma unroll
        for (int ks = 0; ks < 4; ks++) {
            uint32_t ah[4][4], al[4][4];
#pragma unroll
            for (int mi = 0; mi < 4; mi++) {
                uint32_t ad = stb + (wm * 64 + mi * 16 + lr16) * ROWB + ks * 32 + lc16 * 16;
                ldmx4(ah[mi], ad);
                ldmx4(al[mi], ad + PLANE_B);
            }
            uint32_t bh[2][4], bl[2][4];   // [njp][4 regs = nj pair x 2 k-halves]
#pragma unroll
            for (int njp = 0; njp < 2; njp++) {
                uint32_t bd = stb + 2 * PLANE_B + (wn * 32 + njp * 16 + brow) * ROWB + ks * 32 + bcol;
                ldmx4(bh[njp], bd);
                ldmx4(bl[njp], bd + PLANE_B);
            }
#pragma unroll
            for (int mi = 0; mi < 4; mi++)
#pragma unroll
                for (int nj = 0; nj < 4; nj++) {
                    const uint32_t* bhf = &bh[nj >> 1][(nj & 1) * 2];
                    const uint32_t* blf = &bl[nj >> 1][(nj & 1) * 2];
                    mma16816(acc[mi][nj], ah[mi], bhf);
                    mma16816(acc[mi][nj], ah[mi], blf);
                    mma16816(acc[mi][nj], al[mi], bhf);
                }
        }
        __syncthreads();
    }

    // epilogue
    __nv_bfloat16* ph = (z == 0) ? ph0 : (z == 1) ? ph1 : ph2;
    __nv_bfloat16* pl = (z == 0) ? pl0 : (z == 1) ? pl1 : pl2;
    const int tstr = (z == 0) ? SEQ : TTOT;
    const int toff = (z == 0) ? 0 : LCACHE;

#pragma unroll
    for (int nj = 0; nj < 4; nj++) {
        const int n = n0 + wn * 32 + nj * 8 + (lane & 3) * 2;
        const float bx = bias[n], by = bias[n + 1];
        const int h = n >> 6, d = n & 63;
#pragma unroll
        for (int mi = 0; mi < 4; mi++) {
#pragma unroll
            for (int half = 0; half < 2; half++) {
                const int m = m0 + wm * 64 + mi * 16 + (lane >> 2) + half * 8;
                float vx = acc[mi][nj][half * 2] + bx;
                float vy = acc[mi][nj][half * 2 + 1] + by;
                if (headwise) {
                    int b = m >> 10, s = m & 1023;
                    size_t ad = (((size_t)b * NHEADS + h) * tstr + toff + s) * HD + d;
                    __nv_bfloat16 hx = __float2bfloat16_rn(vx);
                    __nv_bfloat16 hy = __float2bfloat16_rn(vy);
                    *(__nv_bfloat162*)(ph + ad) = __halves2bfloat162(hx, hy);
                    *(__nv_bfloat162*)(pl + ad) = __halves2bfloat162(
                        __float2bfloat16_rn(vx - __bfloat162float(hx)),
                        __float2bfloat16_rn(vy - __bfloat162float(hy)));
                } else {
                    *(float2*)&fout[(size_t)m * DM + n] = make_float2(vx, vy);
                }
            }
        }
    }
}

// ---------------------------------------------------------------------------
// Tensor-core flash attention (unchanged from R7).
// ---------------------------------------------------------------------------
#define ASTRIDE 144
#define APLANE  (64 * ASTRIDE)
#define AKVOFF  (2 * APLANE)
#define ASMEM   (2 * APLANE + 2 * 4 * APLANE)
#define SCLOG2  0.18033688011112042f

__global__ __launch_bounds__(128, 2)
void attn_tc()
{
    extern __shared__ char smem[];
    const uint32_t sb = smem_u32(smem);
    const int tid = threadIdx.x, w = tid >> 5, lane = tid & 31;
    const int bh = blockIdx.x;
    const int qt = 15 - blockIdx.y;
    const int q0 = qt * 64;
    const int nt = qt + 17;

#pragma unroll
    for (int it = 0; it < 8; it++) {
        int g = it * 128 + tid;
        int plane = g >> 9, row = (g >> 3) & 63, gc = g & 7;
        const __nv_bfloat16* src = (plane ? g_qlo : g_qhi)
            + ((size_t)bh * SEQ + q0 + row) * HD + gc * 8;
        cp16(sb + plane * APLANE + row * ASTRIDE + gc * 16, src);
    }
    cp_commit();

    auto load_kv = [&](int kt, int st) {
        uint32_t base = sb + AKVOFF + st * (4 * APLANE);
        int t0 = kt * 64;
#pragma unroll
        for (int it = 0; it < 16; it++) {
            int g = it * 128 + tid;
            int plane = g >> 9, row = (g >> 3) & 63, gc = g & 7;
            size_t off = ((size_t)bh * TTOT + t0 + row) * HD + gc * 8;
            const __nv_bfloat16* src;
            if (plane == 0)      src = g_khi + off;
            else if (plane == 1) src = g_klo + off;
            else if (plane == 2) src = g_vhi + off;
            else                 src = g_vlo + off;
            cp16(base + plane * APLANE + row * ASTRIDE + gc * 16, src);
        }
        cp_commit();
    };
    load_kv(0, 0);
    cp_wait<0>();
    __syncthreads();

    uint32_t qh[4][4], ql[4][4];
#pragma unroll
    for (int kc = 0; kc < 4; kc++) {
        uint32_t qa = sb + (w * 16 + (lane & 15)) * ASTRIDE + kc * 32 + (lane >> 4) * 16;
        ldmx4(qh[kc], qa);
        ldmx4(ql[kc], qa + APLANE);
    }

    float oacc[8][4];
#pragma unroll
    for (int i = 0; i < 8; i++)
#pragma unroll
        for (int j = 0; j < 4; j++) oacc[i][j] = 0.f;
    float mrow[2] = {-1e30f, -1e30f}, lrow[2] = {0.f, 0.f};

    for (int kt = 0; kt < nt; kt++) {
        const int st = kt & 1;
        if (kt + 1 < nt) load_kv(kt + 1, st ^ 1);
        const uint32_t kbase = sb + AKVOFF + st * (4 * APLANE);
        const uint32_t vbase = kbase + 2 * APLANE;

        float sacc[8][4];
#pragma unroll
        for (int nb = 0; nb < 8; nb++) {
#pragma unroll
            for (int j = 0; j < 4; j++) sacc[nb][j] = 0.f;
        }
#pragma unroll
        for (int nb = 0; nb < 8; nb++) {
            uint32_t kh[8], kl[8];
            uint32_t ka = kbase + (nb * 8 + (lane & 7)) * ASTRIDE + (lane >> 3) * 16;
            ldmx4(kh, ka);  ldmx4(kh + 4, ka + 64);
            ldmx4(kl, ka + APLANE);  ldmx4(kl + 4, ka + APLANE + 64);
#pragma unroll
            for (int kc = 0; kc < 4; kc++) {
                mma16816(sacc[nb], qh[kc], &kh[kc * 2]);
                mma16816(sacc[nb], qh[kc], &kl[kc * 2]);
                mma16816(sacc[nb], ql[kc], &kh[kc * 2]);
            }
        }

        if (kt == nt - 1) {
            const int qloc = w * 16 + (lane >> 2);
#pragma unroll
            for (int nb = 0; nb < 8; nb++) {
#pragma unroll
                for (int c = 0; c < 4; c++) {
                    int tl = nb * 8 + (lane & 3) * 2 + (c & 1);
                    int qr = qloc + (c >> 1) * 8;
                    if (tl > qr) sacc[nb][c] = -1e30f;
                }
            }
        }

        uint32_t phf[4][4], plf[4][4];
#pragma unroll
        for (int i = 0; i < 2; i++) {
            float mx = -1e30f;
#pragma unroll
            for (int nb = 0; nb < 8; nb++)
                mx = fmaxf(mx, fmaxf(sacc[nb][2 * i], sacc[nb][2 * i + 1]));
            mx = fmaxf(mx, __shfl_xor_sync(0xffffffffu, mx, 1));
            mx = fmaxf(mx, __shfl_xor_sync(0xffffffffu, mx, 2));
            float mn = fmaxf(mrow[i], mx);
            float f = ex2f((mrow[i] - mn) * SCLOG2);
            mrow[i] = mn;
            float sum = 0.f;
#pragma unroll
            for (int nb = 0; nb < 8; nb++) {
                float p0 = ex2f((sacc[nb][2 * i] - mn) * SCLOG2);
                float p1 = ex2f((sacc[nb][2 * i + 1] - mn) * SCLOG2);
                sacc[nb][2 * i] = p0;
                sacc[nb][2 * i + 1] = p1;
                sum += p0 + p1;
            }
            sum += __shfl_xor_sync(0xffffffffu, sum, 1);
            sum += __shfl_xor_sync(0xffffffffu, sum, 2);
            lrow[i] = lrow[i] * f + sum;
#pragma unroll
            for (int nbd = 0; nbd < 8; nbd++) {
                oacc[nbd][2 * i] *= f;
                oacc[nbd][2 * i + 1] *= f;
            }
        }

#pragma unroll
        for (int kc = 0; kc < 4; kc++) {
#pragma unroll
            for (int q = 0; q < 4; q++) {
                int nb = 2 * kc + (q >> 1);
                float a = sacc[nb][(q & 1) * 2];
                float b = sacc[nb][(q & 1) * 2 + 1];
                __nv_bfloat16 ha, hb2;
                phf[kc][q] = pack_hi(a, b, ha, hb2);
                __nv_bfloat162 lo2 = __halves2bfloat162(
                    __float2bfloat16_rn(a - __bfloat162float(ha)),
                    __float2bfloat16_rn(b - __bfloat162float(hb2)));
                plf[kc][q] = *(uint32_t*)&lo2;
            }
        }

#pragma unroll
        for (int kc = 0; kc < 4; kc++) {
#pragma unroll
            for (int dp = 0; dp < 4; dp++) {
                uint32_t vh[4], vl[4];
                uint32_t va = vbase + (kc * 16 + ((lane >> 3) & 1) * 8 + (lane & 7)) * ASTRIDE
                            + (dp * 16 + (lane >> 4) * 8) * 2;
                ldmx4t(vh, va);
                ldmx4t(vl, va + APLANE);
                mma16816(oacc[dp * 2],     phf[kc], &vh[0]);
                mma16816(oacc[dp * 2],     phf[kc], &vl[0]);
                mma16816(oacc[dp * 2],     plf[kc], &vh[0]);
                mma16816(oacc[dp * 2 + 1], phf[kc], &vh[2]);
                mma16816(oacc[dp * 2 + 1], phf[kc], &vl[2]);
                mma16816(oacc[dp * 2 + 1], plf[kc], &vh[2]);
            }
        }

        cp_wait<0>();
        __syncthreads();
    }

    const int b = bh >> 4, h = bh & 15;
#pragma unroll
    for (int i = 0; i < 2; i++) {
        float inv = 1.f / lrow[i];
        int srow = q0 + w * 16 + (lane >> 2) + i * 8;
        size_t mbase = ((size_t)b * SEQ + srow) * DM + h * HD + (lane & 3) * 2;
#pragma unroll
        for (int nbd = 0; nbd < 8; nbd++) {
            float v0 = oacc[nbd][2 * i] * inv;
            float v1 = oacc[nbd][2 * i + 1] * inv;
            __nv_bfloat16 h0 = __float2bfloat16_rn(v0);
            __nv_bfloat16 h1 = __float2bfloat16_rn(v1);
            *(__nv_bfloat162*)(g_ahi + mbase + nbd * 8) = __halves2bfloat162(h0, h1);
            *(__nv_bfloat162*)(g_alo + mbase + nbd * 8) = __halves2bfloat162(
                __float2bfloat16_rn(v0 - __bfloat162float(h0)),
                __float2bfloat16_rn(v1 - __bfloat162float(h1)));
        }
    }
}

// ---------------------------------------------------------------------------
// launch
// ---------------------------------------------------------------------------
extern "C" void kernel_launch(void* const* d_in, const int* in_sizes, int n_in,
                              void* d_out, int out_size)
{
    const float* x  = (const float*)d_in[0];
    const float* ck = (const float*)d_in[1];
    const float* cv = (const float*)d_in[2];
    const float* Wq = (const float*)d_in[3];
    const float* bq = (const float*)d_in[4];
    const float* Wk = (const float*)d_in[5];
    const float* bk = (const float*)d_in[6];
    const float* Wv = (const float*)d_in[7];
    const float* bv = (const float*)d_in[8];
    const float* Wo = (const float*)d_in[9];
    const float* bo = (const float*)d_in[10];
    float* out = (float*)d_out;

    __nv_bfloat16 *xhi, *xlo, *whi, *wlo, *ahi, *alo;
    __nv_bfloat16 *qhi, *qlo, *khi, *klo, *vhi, *vlo;
    cudaGetSymbolAddress((void**)&xhi, g_xhi);
    cudaGetSymbolAddress((void**)&xlo, g_xlo);
    cudaGetSymbolAddress((void**)&whi, g_whi);
    cudaGetSymbolAddress((void**)&wlo, g_wlo);
    cudaGetSymbolAddress((void**)&ahi, g_ahi);
    cudaGetSymbolAddress((void**)&alo, g_alo);
    cudaGetSymbolAddress((void**)&qhi, g_qhi);
    cudaGetSymbolAddress((void**)&qlo, g_qlo);
    cudaGetSymbolAddress((void**)&khi, g_khi);
    cudaGetSymbolAddress((void**)&klo, g_klo);
    cudaGetSymbolAddress((void**)&vhi, g_vhi);
    cudaGetSymbolAddress((void**)&vlo, g_vlo);

    cudaFuncSetAttribute(gemm_mma, cudaFuncAttributeMaxDynamicSharedMemorySize, GSMEM);
    cudaFuncSetAttribute(attn_tc, cudaFuncAttributeMaxDynamicSharedMemorySize, ASMEM);

    // 1) splits + cache conversion
    split_kernel<<<(MROWS * DM / 4 + 255) / 256, 256>>>(x, xhi, xlo, MROWS * DM / 4);
    split_w4<<<dim3(DM * DM / 4 / 256, 4), 256>>>(Wq, Wk, Wv, Wo, whi, wlo);
    convert_cache<<<dim3(BH * LCACHE * HD / 4 / 256, 2), 256>>>(ck, cv);

    // 2) QKV projections -> bf16 hi/lo Q/K/V planes
    gemm_mma<<<dim3(8, 16, 3), 256, GSMEM>>>(xhi, xlo, whi, wlo,
                                             bq, bk, bv,
                                             qhi, qlo, khi, klo, vhi, vlo,
                                             nullptr, 1);

    // 3) tensor-core flash attention -> bf16 hi/lo planes
    attn_tc<<<dim3(BH, 16), 128, ASMEM>>>();

    // 4) output projection -> fp32 d_out
    gemm_mma<<<dim3(8, 16, 1), 256, GSMEM>>>(ahi, alo,
                                             whi + (size_t)3 * DM * DM, wlo + (size_t)3 * DM * DM,
                                             bo, bo, bo,
                                             nullptr, nullptr, nullptr, nullptr, nullptr, nullptr,
                                             out, 0);
}

// round 11
// speedup vs baseline: 1.6099x; 1.4160x over previous
#include <cuda_runtime.h>
#include <cuda_bf16.h>
#include <cstdint>

#define DM     1024
#define NHEADS 16
#define HD     64
#define BATCH  2
#define SEQ    1024
#define LCACHE 1024
#define TTOT   2048
#define BH     (BATCH * NHEADS)   // 32
#define MROWS  (BATCH * SEQ)      // 2048

// ---------------------------------------------------------------------------
// Scratch (device globals; no allocation allowed)
// ---------------------------------------------------------------------------
__device__ __nv_bfloat16 g_xhi[MROWS * DM], g_xlo[MROWS * DM];
__device__ __nv_bfloat16 g_whi[4 * DM * DM], g_wlo[4 * DM * DM];
__device__ __nv_bfloat16 g_qhi[BH * SEQ * HD],  g_qlo[BH * SEQ * HD];
__device__ __nv_bfloat16 g_khi[BH * TTOT * HD], g_klo[BH * TTOT * HD];
__device__ __nv_bfloat16 g_vhi[BH * TTOT * HD], g_vlo[BH * TTOT * HD];
__device__ __nv_bfloat16 g_ahi[MROWS * DM], g_alo[MROWS * DM];

// ---------------------------------------------------------------------------
// PTX helpers — baseline ISA only (compute_103-safe)
// ---------------------------------------------------------------------------
__device__ __forceinline__ uint32_t smem_u32(const void* p) {
    uint32_t a;
    asm("{ .reg .u64 t; cvta.to.shared.u64 t, %1; cvt.u32.u64 %0, t; }"
        : "=r"(a) : "l"(p));
    return a;
}
__device__ __forceinline__ void cp16(uint32_t d, const void* s) {
    asm volatile("cp.async.cg.shared.global [%0], [%1], 16;" :: "r"(d), "l"(s) : "memory");
}
__device__ __forceinline__ void cp_commit() {
    asm volatile("cp.async.commit_group;" ::: "memory");
}
template <int N> __device__ __forceinline__ void cp_wait() {
    asm volatile("cp.async.wait_group %0;" :: "n"(N) : "memory");
}
__device__ __forceinline__ void ldmx4(uint32_t* r, uint32_t a) {
    asm volatile("ldmatrix.sync.aligned.m8n8.x4.shared.b16 {%0,%1,%2,%3}, [%4];"
        : "=r"(r[0]), "=r"(r[1]), "=r"(r[2]), "=r"(r[3]) : "r"(a));
}
__device__ __forceinline__ void ldmx4t(uint32_t* r, uint32_t a) {
    asm volatile("ldmatrix.sync.aligned.m8n8.x4.trans.shared.b16 {%0,%1,%2,%3}, [%4];"
        : "=r"(r[0]), "=r"(r[1]), "=r"(r[2]), "=r"(r[3]) : "r"(a));
}
__device__ __forceinline__ void ldmx2(uint32_t* r, uint32_t a) {
    asm volatile("ldmatrix.sync.aligned.m8n8.x2.shared.b16 {%0,%1}, [%2];"
        : "=r"(r[0]), "=r"(r[1]) : "r"(a));
}
__device__ __forceinline__ void mma16816(float* d, const uint32_t* a, const uint32_t* b) {
    asm volatile(
        "mma.sync.aligned.m16n8k16.row.col.f32.bf16.bf16.f32 "
        "{%0,%1,%2,%3}, {%4,%5,%6,%7}, {%8,%9}, {%0,%1,%2,%3};"
        : "+f"(d[0]), "+f"(d[1]), "+f"(d[2]), "+f"(d[3])
        : "r"(a[0]), "r"(a[1]), "r"(a[2]), "r"(a[3]), "r"(b[0]), "r"(b[1]));
}
__device__ __forceinline__ float ex2f(float x) {
    float y;
    asm("ex2.approx.f32 %0, %1;" : "=f"(y) : "f"(x));
    return y;
}
__device__ __forceinline__ uint32_t pack_hi(float a, float b, __nv_bfloat16& ha, __nv_bfloat16& hb) {
    ha = __float2bfloat16_rn(a);
    hb = __float2bfloat16_rn(b);
    __nv_bfloat162 t = __halves2bfloat162(ha, hb);
    return *(uint32_t*)&t;
}

// ---------------------------------------------------------------------------
// Fused prep: split x, split 4 weights, convert KV cache. One launch.
// Flat grid of 10240 blocks x 256 threads; each thread handles one float4.
//   [0, 2048)     : x      -> g_xhi/g_xlo          (524288 float4)
//   [2048, 6144)  : W p    -> g_whi/g_wlo + p*DM*DM (262144 float4 each)
//   [6144, 8192)  : ck     -> g_khi/g_klo (TTOT layout, t < LCACHE)
//   [8192, 10240) : cv     -> g_vhi/g_vlo
// ---------------------------------------------------------------------------
__device__ __forceinline__ void split4_store(float4 v, __nv_bfloat16* hi, __nv_bfloat16* lo,
                                             size_t elem_off)
{
    __nv_bfloat16 h0 = __float2bfloat16_rn(v.x);
    __nv_bfloat16 h1 = __float2bfloat16_rn(v.y);
    __nv_bfloat16 h2 = __float2bfloat16_rn(v.z);
    __nv_bfloat16 h3 = __float2bfloat16_rn(v.w);
    __nv_bfloat16 l0 = __float2bfloat16_rn(v.x - __bfloat162float(h0));
    __nv_bfloat16 l1 = __float2bfloat16_rn(v.y - __bfloat162float(h1));
    __nv_bfloat16 l2 = __float2bfloat16_rn(v.z - __bfloat162float(h2));
    __nv_bfloat16 l3 = __float2bfloat16_rn(v.w - __bfloat162float(h3));
    *(__nv_bfloat162*)(hi + elem_off)     = __halves2bfloat162(h0, h1);
    *(__nv_bfloat162*)(hi + elem_off + 2) = __halves2bfloat162(h2, h3);
    *(__nv_bfloat162*)(lo + elem_off)     = __halves2bfloat162(l0, l1);
    *(__nv_bfloat162*)(lo + elem_off + 2) = __halves2bfloat162(l2, l3);
}

__global__ void prep_all(const float* __restrict__ x,
                         const float* __restrict__ w0, const float* __restrict__ w1,
                         const float* __restrict__ w2, const float* __restrict__ w3,
                         const float* __restrict__ ck, const float* __restrict__ cv)
{
    const int b = blockIdx.x;
    const int tid = threadIdx.x;
    if (b < 2048) {
        int i = b * 256 + tid;
        split4_store(((const float4*)x)[i], g_xhi, g_xlo, (size_t)i * 4);
    } else if (b < 6144) {
        int p = (b - 2048) >> 10;
        int i = ((b - 2048) & 1023) * 256 + tid;
        const float* src = (p == 0) ? w0 : (p == 1) ? w1 : (p == 2) ? w2 : w3;
        size_t off = (size_t)p * (DM * DM) + (size_t)i * 4;
        split4_store(((const float4*)src)[i], g_whi, g_wlo, off);
    } else {
        int which = (b >= 8192);
        int i = (b - (which ? 8192 : 6144)) * 256 + tid;
        const float* src = which ? cv : ck;
        __nv_bfloat16* hi = which ? g_vhi : g_khi;
        __nv_bfloat16* lo = which ? g_vlo : g_klo;
        int el = i * 4;
        int bh = el >> 16;              // LCACHE*HD = 65536
        int rest = el & 65535;
        size_t o = (size_t)bh * (TTOT * HD) + rest;
        split4_store(((const float4*)src)[i], hi, lo, o);
    }
}

// ---------------------------------------------------------------------------
// Warp-MMA bf16 GEMM (hi/lo 3-term) — exact R7 configuration.
// 256 threads, 8 warps, warp tile 64x32, CTA 128x128, BK=32, 3-stage pipeline.
// ---------------------------------------------------------------------------
#define ST       3
#define CHUNKS   32
#define ROWPAD   80
#define PLANE_B  (128 * ROWPAD)
#define STAGE_B  (4 * PLANE_B)
#define GSMEM    (ST * STAGE_B)

__global__ __launch_bounds__(256, 1)
void gemm_mma(const __nv_bfloat16* __restrict__ Ahi, const __nv_bfloat16* __restrict__ Alo,
              const __nv_bfloat16* __restrict__ Whi, const __nv_bfloat16* __restrict__ Wlo,
              const float* __restrict__ b0, const float* __restrict__ b1, const float* __restrict__ b2,
              __nv_bfloat16* __restrict__ ph0, __nv_bfloat16* __restrict__ pl0,
              __nv_bfloat16* __restrict__ ph1, __nv_bfloat16* __restrict__ pl1,
              __nv_bfloat16* __restrict__ ph2, __nv_bfloat16* __restrict__ pl2,
              float* __restrict__ fout, int headwise)
{
    extern __shared__ char smem[];
    const uint32_t sb = smem_u32(smem);
    const int tid = threadIdx.x, wid = tid >> 5, lane = tid & 31;
    const int n0 = blockIdx.x * 128, m0 = blockIdx.y * 128, z = blockIdx.z;
    const __nv_bfloat16* Wh = Whi + (size_t)z * DM * DM;
    const __nv_bfloat16* Wl = Wlo + (size_t)z * DM * DM;
    const float* bias = (z == 0) ? b0 : (z == 1) ? b1 : b2;

    const int wm = wid & 1;
    const int wn = wid >> 1;

    auto load_chunk = [&](int stage, int koff) {
        const uint32_t base = sb + stage * STAGE_B;
#pragma unroll
        for (int it = 0; it < 8; it++) {
            int g = it * 256 + tid;
            int plane = g >> 9;
            int row = (g >> 2) & 127;
            int c = g & 3;
            uint32_t dst = base + plane * PLANE_B + row * ROWPAD + c * 16;
            const __nv_bfloat16* src;
            if (plane == 0)      src = Ahi + (size_t)(m0 + row) * DM + koff + c * 8;
            else if (plane == 1) src = Alo + (size_t)(m0 + row) * DM + koff + c * 8;
            else if (plane == 2) src = Wh  + (size_t)(n0 + row) * DM + koff + c * 8;
            else                 src = Wl  + (size_t)(n0 + row) * DM + koff + c * 8;
            cp16(dst, src);
        }
        cp_commit();
    };

    load_chunk(0, 0);
    load_chunk(1, 32);

    float acc[4][4][4];
#pragma unroll
    for (int i = 0; i < 4; i++)
#pragma unroll
        for (int j = 0; j < 4; j++)
#pragma unroll
            for (int r = 0; r < 4; r++) acc[i][j][r] = 0.f;

    const int lr16 = lane & 15, lc16 = lane >> 4;
    const int br8 = lane & 7, bc8 = (lane >> 3) & 1;

    for (int i = 0; i < CHUNKS; i++) {
        if (i + 2 < CHUNKS) load_chunk((i + 2) % ST, (i + 2) * 32);
        else cp_commit();
        cp_wait<2>();
        __syncthreads();

        const uint32_t stb = sb + (i % ST) * STAGE_B;
#pragma unroll
        for (int ks = 0; ks < 2; ks++) {
            uint32_t ah[4][4], al[4][4];
#pragma unroll
            for (int mi = 0; mi < 4; mi++) {
                uint32_t ad = stb + (wm * 64 + mi * 16 + lr16) * ROWPAD + ks * 32 + lc16 * 16;
                ldmx4(ah[mi], ad);
                ldmx4(al[mi], ad + PLANE_B);
            }
            uint32_t bh[4][2], bl[4][2];
#pragma unroll
            for (int nj = 0; nj < 4; nj++) {
                uint32_t bd = stb + 2 * PLANE_B + (wn * 32 + nj * 8 + br8) * ROWPAD + ks * 32 + bc8 * 16;
                ldmx2(bh[nj], bd);
                ldmx2(bl[nj], bd + PLANE_B);
            }
#pragma unroll
            for (int mi = 0; mi < 4; mi++)
#pragma unroll
                for (int nj = 0; nj < 4; nj++) {
                    mma16816(acc[mi][nj], ah[mi], bh[nj]);
                    mma16816(acc[mi][nj], ah[mi], bl[nj]);
                    mma16816(acc[mi][nj], al[mi], bh[nj]);
                }
        }
        __syncthreads();
    }

    // epilogue
    __nv_bfloat16* ph = (z == 0) ? ph0 : (z == 1) ? ph1 : ph2;
    __nv_bfloat16* pl = (z == 0) ? pl0 : (z == 1) ? pl1 : pl2;
    const int tstr = (z == 0) ? SEQ : TTOT;
    const int toff = (z == 0) ? 0 : LCACHE;

#pragma unroll
    for (int nj = 0; nj < 4; nj++) {
        const int n = n0 + wn * 32 + nj * 8 + (lane & 3) * 2;
        const float bx = bias[n], by = bias[n + 1];
        const int h = n >> 6, d = n & 63;
#pragma unroll
        for (int mi = 0; mi < 4; mi++) {
#pragma unroll
            for (int half = 0; half < 2; half++) {
                const int m = m0 + wm * 64 + mi * 16 + (lane >> 2) + half * 8;
                float vx = acc[mi][nj][half * 2] + bx;
                float vy = acc[mi][nj][half * 2 + 1] + by;
                if (headwise) {
                    int b = m >> 10, s = m & 1023;
                    size_t ad = (((size_t)b * NHEADS + h) * tstr + toff + s) * HD + d;
                    __nv_bfloat16 hx = __float2bfloat16_rn(vx);
                    __nv_bfloat16 hy = __float2bfloat16_rn(vy);
                    *(__nv_bfloat162*)(ph + ad) = __halves2bfloat162(hx, hy);
                    *(__nv_bfloat162*)(pl + ad) = __halves2bfloat162(
                        __float2bfloat16_rn(vx - __bfloat162float(hx)),
                        __float2bfloat16_rn(vy - __bfloat162float(hy)));
                } else {
                    *(float2*)&fout[(size_t)m * DM + n] = make_float2(vx, vy);
                }
            }
        }
    }
}

// ---------------------------------------------------------------------------
// Tensor-core flash attention, 128-row q tiles: 256 threads / 8 warps per CTA,
// each warp owns 16 q rows (same per-warp layout as R7). KV tiles of 64,
// double-buffered. One KV load now serves 128 q rows (halved KV traffic).
// ---------------------------------------------------------------------------
#define ASTRIDE  144
#define QPLANE   (128 * ASTRIDE)            // 18432
#define KVPLANE  (64 * ASTRIDE)             // 9216
#define AKVOFF   (2 * QPLANE)               // 36864
#define KVSTAGE  (4 * KVPLANE)              // 36864
#define ASMEM    (2 * QPLANE + 2 * KVSTAGE) // 110592
#define SCLOG2   0.18033688011112042f       // 0.125 * log2(e)

__global__ __launch_bounds__(256, 1)
void attn_tc()
{
    extern __shared__ char smem[];
    const uint32_t sb = smem_u32(smem);
    const int tid = threadIdx.x, w = tid >> 5, lane = tid & 31;
    const int bh = blockIdx.x;
    const int j = 7 - blockIdx.y;          // long tiles first
    const int q0 = j * 128;
    const int nt = 2 * j + 18;

    // Q tile: 2 planes x 128 rows x 128B
#pragma unroll
    for (int it = 0; it < 8; it++) {
        int g = it * 256 + tid;
        int plane = g >> 10, row = (g >> 3) & 127, gc = g & 7;
        const __nv_bfloat16* src = (plane ? g_qlo : g_qhi)
            + ((size_t)bh * SEQ + q0 + row) * HD + gc * 8;
        cp16(sb + plane * QPLANE + row * ASTRIDE + gc * 16, src);
    }
    cp_commit();

    auto load_kv = [&](int kt, int st) {
        uint32_t base = sb + AKVOFF + st * KVSTAGE;
        int t0 = kt * 64;
#pragma unroll
        for (int it = 0; it < 8; it++) {
            int g = it * 256 + tid;
            int plane = g >> 9, row = (g >> 3) & 63, gc = g & 7;
            size_t off = ((size_t)bh * TTOT + t0 + row) * HD + gc * 8;
            const __nv_bfloat16* src;
            if (plane == 0)      src = g_khi + off;
            else if (plane == 1) src = g_klo + off;
            else if (plane == 2) src = g_vhi + off;
            else                 src = g_vlo + off;
            cp16(base + plane * KVPLANE + row * ASTRIDE + gc * 16, src);
        }
        cp_commit();
    };
    load_kv(0, 0);
    cp_wait<0>();
    __syncthreads();

    // Q fragments (A layout), warp w owns rows w*16..w*16+15
    uint32_t qh[4][4], ql[4][4];
#pragma unroll
    for (int kc = 0; kc < 4; kc++) {
        uint32_t qa = sb + (w * 16 + (lane & 15)) * ASTRIDE + kc * 32 + (lane >> 4) * 16;
        ldmx4(qh[kc], qa);
        ldmx4(ql[kc], qa + QPLANE);
    }

    float oacc[8][4];
#pragma unroll
    for (int i = 0; i < 8; i++)
#pragma unroll
        for (int jj = 0; jj < 4; jj++) oacc[i][jj] = 0.f;
    float mrow[2] = {-1e30f, -1e30f}, lrow[2] = {0.f, 0.f};

    const int qrow_base = q0 + w * 16 + (lane >> 2);   // +8 for c>>1 half

    for (int kt = 0; kt < nt; kt++) {
        const int st = kt & 1;
        if (kt + 1 < nt) load_kv(kt + 1, st ^ 1);
        const uint32_t kbase = sb + AKVOFF + st * KVSTAGE;
        const uint32_t vbase = kbase + 2 * KVPLANE;

        // ---- S = Q K^T (3-term)
        float sacc[8][4];
#pragma unroll
        for (int nb = 0; nb < 8; nb++) {
#pragma unroll
            for (int jj = 0; jj < 4; jj++) sacc[nb][jj] = 0.f;
        }
#pragma unroll
        for (int nb = 0; nb < 8; nb++) {
            uint32_t kh[8], kl[8];
            uint32_t ka = kbase + (nb * 8 + (lane & 7)) * ASTRIDE + (lane >> 3) * 16;
            ldmx4(kh, ka);  ldmx4(kh + 4, ka + 64);
            ldmx4(kl, ka + KVPLANE);  ldmx4(kl + 4, ka + KVPLANE + 64);
#pragma unroll
            for (int kc = 0; kc < 4; kc++) {
                mma16816(sacc[nb], qh[kc], &kh[kc * 2]);
                mma16816(sacc[nb], qh[kc], &kl[kc * 2]);
                mma16816(sacc[nb], ql[kc], &kh[kc * 2]);
            }
        }

        // ---- causal mask: last two tiles may be partial (t > q + 1024)
        if (kt >= nt - 2) {
            const int t0g = kt * 64;
#pragma unroll
            for (int nb = 0; nb < 8; nb++) {
#pragma unroll
                for (int c = 0; c < 4; c++) {
                    int tgl = t0g + nb * 8 + (lane & 3) * 2 + (c & 1);
                    int qgl = qrow_base + (c >> 1) * 8;
                    if (tgl > qgl + LCACHE) sacc[nb][c] = -1e30f;
                }
            }
        }

        // ---- online softmax (2 rows per thread)
        uint32_t phf[4][4], plf[4][4];
#pragma unroll
        for (int i = 0; i < 2; i++) {
            float mx = -1e30f;
#pragma unroll
            for (int nb = 0; nb < 8; nb++)
                mx = fmaxf(mx, fmaxf(sacc[nb][2 * i], sacc[nb][2 * i + 1]));
            mx = fmaxf(mx, __shfl_xor_sync(0xffffffffu, mx, 1));
            mx = fmaxf(mx, __shfl_xor_sync(0xffffffffu, mx, 2));
            float mn = fmaxf(mrow[i], mx);
            float f = ex2f((mrow[i] - mn) * SCLOG2);
            mrow[i] = mn;
            float sum = 0.f;
#pragma unroll
            for (int nb = 0; nb < 8; nb++) {
                float p0 = ex2f((sacc[nb][2 * i] - mn) * SCLOG2);
                float p1 = ex2f((sacc[nb][2 * i + 1] - mn) * SCLOG2);
                sacc[nb][2 * i] = p0;
                sacc[nb][2 * i + 1] = p1;
                sum += p0 + p1;
            }
            sum += __shfl_xor_sync(0xffffffffu, sum, 1);
            sum += __shfl_xor_sync(0xffffffffu, sum, 2);
            lrow[i] = lrow[i] * f + sum;
#pragma unroll
            for (int nbd = 0; nbd < 8; nbd++) {
                oacc[nbd][2 * i] *= f;
                oacc[nbd][2 * i + 1] *= f;
            }
        }

        // ---- P -> A fragments (register-only), hi/lo
#pragma unroll
        for (int kc = 0; kc < 4; kc++) {
#pragma unroll
            for (int q = 0; q < 4; q++) {
                int nb = 2 * kc + (q >> 1);
                float a = sacc[nb][(q & 1) * 2];
                float b = sacc[nb][(q & 1) * 2 + 1];
                __nv_bfloat16 ha, hb2;
                phf[kc][q] = pack_hi(a, b, ha, hb2);
                __nv_bfloat162 lo2 = __halves2bfloat162(
                    __float2bfloat16_rn(a - __bfloat162float(ha)),
                    __float2bfloat16_rn(b - __bfloat162float(hb2)));
                plf[kc][q] = *(uint32_t*)&lo2;
            }
        }

        // ---- O += P V (3-term), V via ldmatrix.trans
#pragma unroll
        for (int kc = 0; kc < 4; kc++) {
#pragma unroll
            for (int dp = 0; dp < 4; dp++) {
                uint32_t vh[4], vl[4];
                uint32_t va = vbase + (kc * 16 + ((lane >> 3) & 1) * 8 + (lane & 7)) * ASTRIDE
                            + (dp * 16 + (lane >> 4) * 8) * 2;
                ldmx4t(vh, va);
                ldmx4t(vl, va + KVPLANE);
                mma16816(oacc[dp * 2],     phf[kc], &vh[0]);
                mma16816(oacc[dp * 2],     phf[kc], &vl[0]);
                mma16816(oacc[dp * 2],     plf[kc], &vh[0]);
                mma16816(oacc[dp * 2 + 1], phf[kc], &vh[2]);
                mma16816(oacc[dp * 2 + 1], phf[kc], &vl[2]);
                mma16816(oacc[dp * 2 + 1], plf[kc], &vh[2]);
            }
        }

        cp_wait<0>();
        __syncthreads();
    }

    // ---- epilogue: normalize, write bf16 hi/lo planes for oproj
    const int b = bh >> 4, h = bh & 15;
#pragma unroll
    for (int i = 0; i < 2; i++) {
        float inv = 1.f / lrow[i];
        int srow = q0 + w * 16 + (lane >> 2) + i * 8;
        size_t mbase = ((size_t)b * SEQ + srow) * DM + h * HD + (lane & 3) * 2;
#pragma unroll
        for (int nbd = 0; nbd < 8; nbd++) {
            float v0 = oacc[nbd][2 * i] * inv;
            float v1 = oacc[nbd][2 * i + 1] * inv;
            __nv_bfloat16 h0 = __float2bfloat16_rn(v0);
            __nv_bfloat16 h1 = __float2bfloat16_rn(v1);
            *(__nv_bfloat162*)(g_ahi + mbase + nbd * 8) = __halves2bfloat162(h0, h1);
            *(__nv_bfloat162*)(g_alo + mbase + nbd * 8) = __halves2bfloat162(
                __float2bfloat16_rn(v0 - __bfloat162float(h0)),
                __float2bfloat16_rn(v1 - __bfloat162float(h1)));
        }
    }
}

// ---------------------------------------------------------------------------
// launch
// ---------------------------------------------------------------------------
extern "C" void kernel_launch(void* const* d_in, const int* in_sizes, int n_in,
                              void* d_out, int out_size)
{
    const float* x  = (const float*)d_in[0];
    const float* ck = (const float*)d_in[1];
    const float* cv = (const float*)d_in[2];
    const float* Wq = (const float*)d_in[3];
    const float* bq = (const float*)d_in[4];
    const float* Wk = (const float*)d_in[5];
    const float* bk = (const float*)d_in[6];
    const float* Wv = (const float*)d_in[7];
    const float* bv = (const float*)d_in[8];
    const float* Wo = (const float*)d_in[9];
    const float* bo = (const float*)d_in[10];
    float* out = (float*)d_out;

    __nv_bfloat16 *xhi, *xlo, *whi, *wlo, *ahi, *alo;
    __nv_bfloat16 *qhi, *qlo, *khi, *klo, *vhi, *vlo;
    cudaGetSymbolAddress((void**)&xhi, g_xhi);
    cudaGetSymbolAddress((void**)&xlo, g_xlo);
    cudaGetSymbolAddress((void**)&whi, g_whi);
    cudaGetSymbolAddress((void**)&wlo, g_wlo);
    cudaGetSymbolAddress((void**)&ahi, g_ahi);
    cudaGetSymbolAddress((void**)&alo, g_alo);
    cudaGetSymbolAddress((void**)&qhi, g_qhi);
    cudaGetSymbolAddress((void**)&qlo, g_qlo);
    cudaGetSymbolAddress((void**)&khi, g_khi);
    cudaGetSymbolAddress((void**)&klo, g_klo);
    cudaGetSymbolAddress((void**)&vhi, g_vhi);
    cudaGetSymbolAddress((void**)&vlo, g_vlo);

    cudaFuncSetAttribute(gemm_mma, cudaFuncAttributeMaxDynamicSharedMemorySize, GSMEM);
    cudaFuncSetAttribute(attn_tc, cudaFuncAttributeMaxDynamicSharedMemorySize, ASMEM);

    // 1) fused prep: splits + cache conversion (one launch)
    prep_all<<<10240, 256>>>(x, Wq, Wk, Wv, Wo, ck, cv);

    // 2) QKV projections -> bf16 hi/lo Q/K/V planes
    gemm_mma<<<dim3(8, 16, 3), 256, GSMEM>>>(xhi, xlo, whi, wlo,
                                             bq, bk, bv,
                                             qhi, qlo, khi, klo, vhi, vlo,
                                             nullptr, 1);

    // 3) tensor-core flash attention (128-row q tiles) -> bf16 hi/lo planes
    attn_tc<<<dim3(BH, 8), 256, ASMEM>>>();

    // 4) output projection -> fp32 d_out
    gemm_mma<<<dim3(8, 16, 1), 256, GSMEM>>>(ahi, alo,
                                             whi + (size_t)3 * DM * DM, wlo + (size_t)3 * DM * DM,
                                             bo, bo, bo,
                                             nullptr, nullptr, nullptr, nullptr, nullptr, nullptr,
                                             out, 0);
}

// round 12
// speedup vs baseline: 1.7579x; 1.0920x over previous
#include <cuda_runtime.h>
#include <cuda_bf16.h>
#include <cstdint>

#define DM     1024
#define NHEADS 16
#define HD     64
#define BATCH  2
#define SEQ    1024
#define LCACHE 1024
#define TTOT   2048
#define BH     (BATCH * NHEADS)   // 32
#define MROWS  (BATCH * SEQ)      // 2048

// ---------------------------------------------------------------------------
// Scratch (device globals; no allocation allowed)
// ---------------------------------------------------------------------------
__device__ __nv_bfloat16 g_xhi[MROWS * DM], g_xlo[MROWS * DM];
__device__ __nv_bfloat16 g_whi[4 * DM * DM], g_wlo[4 * DM * DM];
__device__ __nv_bfloat16 g_qhi[BH * SEQ * HD],  g_qlo[BH * SEQ * HD];
__device__ __nv_bfloat16 g_khi[BH * TTOT * HD], g_klo[BH * TTOT * HD];
__device__ __nv_bfloat16 g_vhi[BH * TTOT * HD], g_vlo[BH * TTOT * HD];
__device__ __nv_bfloat16 g_ahi[MROWS * DM], g_alo[MROWS * DM];

// ---------------------------------------------------------------------------
// PTX helpers — baseline ISA only (compute_103-safe)
// ---------------------------------------------------------------------------
__device__ __forceinline__ uint32_t smem_u32(const void* p) {
    uint32_t a;
    asm("{ .reg .u64 t; cvta.to.shared.u64 t, %1; cvt.u32.u64 %0, t; }"
        : "=r"(a) : "l"(p));
    return a;
}
__device__ __forceinline__ void cp16(uint32_t d, const void* s) {
    asm volatile("cp.async.cg.shared.global [%0], [%1], 16;" :: "r"(d), "l"(s) : "memory");
}
__device__ __forceinline__ void cp_commit() {
    asm volatile("cp.async.commit_group;" ::: "memory");
}
template <int N> __device__ __forceinline__ void cp_wait() {
    asm volatile("cp.async.wait_group %0;" :: "n"(N) : "memory");
}
__device__ __forceinline__ void ldmx4(uint32_t* r, uint32_t a) {
    asm volatile("ldmatrix.sync.aligned.m8n8.x4.shared.b16 {%0,%1,%2,%3}, [%4];"
        : "=r"(r[0]), "=r"(r[1]), "=r"(r[2]), "=r"(r[3]) : "r"(a));
}
__device__ __forceinline__ void ldmx4t(uint32_t* r, uint32_t a) {
    asm volatile("ldmatrix.sync.aligned.m8n8.x4.trans.shared.b16 {%0,%1,%2,%3}, [%4];"
        : "=r"(r[0]), "=r"(r[1]), "=r"(r[2]), "=r"(r[3]) : "r"(a));
}
__device__ __forceinline__ void ldmx2(uint32_t* r, uint32_t a) {
    asm volatile("ldmatrix.sync.aligned.m8n8.x2.shared.b16 {%0,%1}, [%2];"
        : "=r"(r[0]), "=r"(r[1]) : "r"(a));
}
__device__ __forceinline__ void mma16816(float* d, const uint32_t* a, const uint32_t* b) {
    asm volatile(
        "mma.sync.aligned.m16n8k16.row.col.f32.bf16.bf16.f32 "
        "{%0,%1,%2,%3}, {%4,%5,%6,%7}, {%8,%9}, {%0,%1,%2,%3};"
        : "+f"(d[0]), "+f"(d[1]), "+f"(d[2]), "+f"(d[3])
        : "r"(a[0]), "r"(a[1]), "r"(a[2]), "r"(a[3]), "r"(b[0]), "r"(b[1]));
}
__device__ __forceinline__ float ex2f(float x) {
    float y;
    asm("ex2.approx.f32 %0, %1;" : "=f"(y) : "f"(x));
    return y;
}
__device__ __forceinline__ uint32_t pack_hi(float a, float b, __nv_bfloat16& ha, __nv_bfloat16& hb) {
    ha = __float2bfloat16_rn(a);
    hb = __float2bfloat16_rn(b);
    __nv_bfloat162 t = __halves2bfloat162(ha, hb);
    return *(uint32_t*)&t;
}

// ---------------------------------------------------------------------------
// Fused prep: split x, split 4 weights, convert KV cache. One launch.
// ---------------------------------------------------------------------------
__device__ __forceinline__ void split4_store(float4 v, __nv_bfloat16* hi, __nv_bfloat16* lo,
                                             size_t elem_off)
{
    __nv_bfloat16 h0 = __float2bfloat16_rn(v.x);
    __nv_bfloat16 h1 = __float2bfloat16_rn(v.y);
    __nv_bfloat16 h2 = __float2bfloat16_rn(v.z);
    __nv_bfloat16 h3 = __float2bfloat16_rn(v.w);
    __nv_bfloat16 l0 = __float2bfloat16_rn(v.x - __bfloat162float(h0));
    __nv_bfloat16 l1 = __float2bfloat16_rn(v.y - __bfloat162float(h1));
    __nv_bfloat16 l2 = __float2bfloat16_rn(v.z - __bfloat162float(h2));
    __nv_bfloat16 l3 = __float2bfloat16_rn(v.w - __bfloat162float(h3));
    *(__nv_bfloat162*)(hi + elem_off)     = __halves2bfloat162(h0, h1);
    *(__nv_bfloat162*)(hi + elem_off + 2) = __halves2bfloat162(h2, h3);
    *(__nv_bfloat162*)(lo + elem_off)     = __halves2bfloat162(l0, l1);
    *(__nv_bfloat162*)(lo + elem_off + 2) = __halves2bfloat162(l2, l3);
}

__global__ void prep_all(const float* __restrict__ x,
                         const float* __restrict__ w0, const float* __restrict__ w1,
                         const float* __restrict__ w2, const float* __restrict__ w3,
                         const float* __restrict__ ck, const float* __restrict__ cv)
{
    const int b = blockIdx.x;
    const int tid = threadIdx.x;
    if (b < 2048) {
        int i = b * 256 + tid;
        split4_store(((const float4*)x)[i], g_xhi, g_xlo, (size_t)i * 4);
    } else if (b < 6144) {
        int p = (b - 2048) >> 10;
        int i = ((b - 2048) & 1023) * 256 + tid;
        const float* src = (p == 0) ? w0 : (p == 1) ? w1 : (p == 2) ? w2 : w3;
        size_t off = (size_t)p * (DM * DM) + (size_t)i * 4;
        split4_store(((const float4*)src)[i], g_whi, g_wlo, off);
    } else {
        int which = (b >= 8192);
        int i = (b - (which ? 8192 : 6144)) * 256 + tid;
        const float* src = which ? cv : ck;
        __nv_bfloat16* hi = which ? g_vhi : g_khi;
        __nv_bfloat16* lo = which ? g_vlo : g_klo;
        int el = i * 4;
        int bh = el >> 16;              // LCACHE*HD = 65536
        int rest = el & 65535;
        size_t o = (size_t)bh * (TTOT * HD) + rest;
        split4_store(((const float4*)src)[i], hi, lo, o);
    }
}

// ---------------------------------------------------------------------------
// Warp-MMA bf16 GEMM (hi/lo 3-term) — R7 tile config, ONE barrier per chunk.
// 256 threads, 8 warps, warp tile 64x32, CTA 128x128, BK=32, 3-stage pipeline.
// Mainloop: wait<1>; barrier; compute(i); load(i+2). Race-free: a warp reaches
// load(i+2) (writes stage (i-1)%3) only after the iter-i barrier, which all
// warps pass only after finishing compute(i-1) on that stage.
// ---------------------------------------------------------------------------
#define ST       3
#define CHUNKS   32
#define ROWPAD   80
#define PLANE_B  (128 * ROWPAD)
#define STAGE_B  (4 * PLANE_B)
#define GSMEM    (ST * STAGE_B)

__global__ __launch_bounds__(256, 1)
void gemm_mma(const __nv_bfloat16* __restrict__ Ahi, const __nv_bfloat16* __restrict__ Alo,
              const __nv_bfloat16* __restrict__ Whi, const __nv_bfloat16* __restrict__ Wlo,
              const float* __restrict__ b0, const float* __restrict__ b1, const float* __restrict__ b2,
              __nv_bfloat16* __restrict__ ph0, __nv_bfloat16* __restrict__ pl0,
              __nv_bfloat16* __restrict__ ph1, __nv_bfloat16* __restrict__ pl1,
              __nv_bfloat16* __restrict__ ph2, __nv_bfloat16* __restrict__ pl2,
              float* __restrict__ fout, int headwise)
{
    extern __shared__ char smem[];
    const uint32_t sb = smem_u32(smem);
    const int tid = threadIdx.x, wid = tid >> 5, lane = tid & 31;
    const int n0 = blockIdx.x * 128, m0 = blockIdx.y * 128, z = blockIdx.z;
    const __nv_bfloat16* Wh = Whi + (size_t)z * DM * DM;
    const __nv_bfloat16* Wl = Wlo + (size_t)z * DM * DM;
    const float* bias = (z == 0) ? b0 : (z == 1) ? b1 : b2;

    const int wm = wid & 1;
    const int wn = wid >> 1;

    auto load_chunk = [&](int stage, int koff) {
        const uint32_t base = sb + stage * STAGE_B;
#pragma unroll
        for (int it = 0; it < 8; it++) {
            int g = it * 256 + tid;
            int plane = g >> 9;
            int row = (g >> 2) & 127;
            int c = g & 3;
            uint32_t dst = base + plane * PLANE_B + row * ROWPAD + c * 16;
            const __nv_bfloat16* src;
            if (plane == 0)      src = Ahi + (size_t)(m0 + row) * DM + koff + c * 8;
            else if (plane == 1) src = Alo + (size_t)(m0 + row) * DM + koff + c * 8;
            else if (plane == 2) src = Wh  + (size_t)(n0 + row) * DM + koff + c * 8;
            else                 src = Wl  + (size_t)(n0 + row) * DM + koff + c * 8;
            cp16(dst, src);
        }
        cp_commit();
    };

    load_chunk(0, 0);
    load_chunk(1, 32);

    float acc[4][4][4];
#pragma unroll
    for (int i = 0; i < 4; i++)
#pragma unroll
        for (int j = 0; j < 4; j++)
#pragma unroll
            for (int r = 0; r < 4; r++) acc[i][j][r] = 0.f;

    const int lr16 = lane & 15, lc16 = lane >> 4;
    const int br8 = lane & 7, bc8 = (lane >> 3) & 1;

    for (int i = 0; i < CHUNKS; i++) {
        cp_wait<1>();
        __syncthreads();

        const uint32_t stb = sb + (i % ST) * STAGE_B;
#pragma unroll
        for (int ks = 0; ks < 2; ks++) {
            uint32_t ah[4][4], al[4][4];
#pragma unroll
            for (int mi = 0; mi < 4; mi++) {
                uint32_t ad = stb + (wm * 64 + mi * 16 + lr16) * ROWPAD + ks * 32 + lc16 * 16;
                ldmx4(ah[mi], ad);
                ldmx4(al[mi], ad + PLANE_B);
            }
            uint32_t bh[4][2], bl[4][2];
#pragma unroll
            for (int nj = 0; nj < 4; nj++) {
                uint32_t bd = stb + 2 * PLANE_B + (wn * 32 + nj * 8 + br8) * ROWPAD + ks * 32 + bc8 * 16;
                ldmx2(bh[nj], bd);
                ldmx2(bl[nj], bd + PLANE_B);
            }
#pragma unroll
            for (int mi = 0; mi < 4; mi++)
#pragma unroll
                for (int nj = 0; nj < 4; nj++) {
                    mma16816(acc[mi][nj], ah[mi], bh[nj]);
                    mma16816(acc[mi][nj], ah[mi], bl[nj]);
                    mma16816(acc[mi][nj], al[mi], bh[nj]);
                }
        }

        if (i + 2 < CHUNKS) load_chunk((i + 2) % ST, (i + 2) * 32);
        else cp_commit();   // keep per-thread group counts uniform for cp_wait<1>
    }

    // epilogue
    __nv_bfloat16* ph = (z == 0) ? ph0 : (z == 1) ? ph1 : ph2;
    __nv_bfloat16* pl = (z == 0) ? pl0 : (z == 1) ? pl1 : pl2;
    const int tstr = (z == 0) ? SEQ : TTOT;
    const int toff = (z == 0) ? 0 : LCACHE;

#pragma unroll
    for (int nj = 0; nj < 4; nj++) {
        const int n = n0 + wn * 32 + nj * 8 + (lane & 3) * 2;
        const float bx = bias[n], by = bias[n + 1];
        const int h = n >> 6, d = n & 63;
#pragma unroll
        for (int mi = 0; mi < 4; mi++) {
#pragma unroll
            for (int half = 0; half < 2; half++) {
                const int m = m0 + wm * 64 + mi * 16 + (lane >> 2) + half * 8;
                float vx = acc[mi][nj][half * 2] + bx;
                float vy = acc[mi][nj][half * 2 + 1] + by;
                if (headwise) {
                    int b = m >> 10, s = m & 1023;
                    size_t ad = (((size_t)b * NHEADS + h) * tstr + toff + s) * HD + d;
                    __nv_bfloat16 hx = __float2bfloat16_rn(vx);
                    __nv_bfloat16 hy = __float2bfloat16_rn(vy);
                    *(__nv_bfloat162*)(ph + ad) = __halves2bfloat162(hx, hy);
                    *(__nv_bfloat162*)(pl + ad) = __halves2bfloat162(
                        __float2bfloat16_rn(vx - __bfloat162float(hx)),
                        __float2bfloat16_rn(vy - __bfloat162float(hy)));
                } else {
                    *(float2*)&fout[(size_t)m * DM + n] = make_float2(vx, vy);
                }
            }
        }
    }
}

// ---------------------------------------------------------------------------
// Tensor-core flash attention, 128-row q tiles (unchanged from R11).
// ---------------------------------------------------------------------------
#define ASTRIDE  144
#define QPLANE   (128 * ASTRIDE)
#define KVPLANE  (64 * ASTRIDE)
#define AKVOFF   (2 * QPLANE)
#define KVSTAGE  (4 * KVPLANE)
#define ASMEM    (2 * QPLANE + 2 * KVSTAGE)
#define SCLOG2   0.18033688011112042f

__global__ __launch_bounds__(256, 1)
void attn_tc()
{
    extern __shared__ char smem[];
    const uint32_t sb = smem_u32(smem);
    const int tid = threadIdx.x, w = tid >> 5, lane = tid & 31;
    const int bh = blockIdx.x;
    const int j = 7 - blockIdx.y;
    const int q0 = j * 128;
    const int nt = 2 * j + 18;

#pragma unroll
    for (int it = 0; it < 8; it++) {
        int g = it * 256 + tid;
        int plane = g >> 10, row = (g >> 3) & 127, gc = g & 7;
        const __nv_bfloat16* src = (plane ? g_qlo : g_qhi)
            + ((size_t)bh * SEQ + q0 + row) * HD + gc * 8;
        cp16(sb + plane * QPLANE + row * ASTRIDE + gc * 16, src);
    }
    cp_commit();

    auto load_kv = [&](int kt, int st) {
        uint32_t base = sb + AKVOFF + st * KVSTAGE;
        int t0 = kt * 64;
#pragma unroll
        for (int it = 0; it < 8; it++) {
            int g = it * 256 + tid;
            int plane = g >> 9, row = (g >> 3) & 63, gc = g & 7;
            size_t off = ((size_t)bh * TTOT + t0 + row) * HD + gc * 8;
            const __nv_bfloat16* src;
            if (plane == 0)      src = g_khi + off;
            else if (plane == 1) src = g_klo + off;
            else if (plane == 2) src = g_vhi + off;
            else                 src = g_vlo + off;
            cp16(base + plane * KVPLANE + row * ASTRIDE + gc * 16, src);
        }
        cp_commit();
    };
    load_kv(0, 0);
    cp_wait<0>();
    __syncthreads();

    uint32_t qh[4][4], ql[4][4];
#pragma unroll
    for (int kc = 0; kc < 4; kc++) {
        uint32_t qa = sb + (w * 16 + (lane & 15)) * ASTRIDE + kc * 32 + (lane >> 4) * 16;
        ldmx4(qh[kc], qa);
        ldmx4(ql[kc], qa + QPLANE);
    }

    float oacc[8][4];
#pragma unroll
    for (int i = 0; i < 8; i++)
#pragma unroll
        for (int jj = 0; jj < 4; jj++) oacc[i][jj] = 0.f;
    float mrow[2] = {-1e30f, -1e30f}, lrow[2] = {0.f, 0.f};

    const int qrow_base = q0 + w * 16 + (lane >> 2);

    for (int kt = 0; kt < nt; kt++) {
        const int st = kt & 1;
        if (kt + 1 < nt) load_kv(kt + 1, st ^ 1);
        const uint32_t kbase = sb + AKVOFF + st * KVSTAGE;
        const uint32_t vbase = kbase + 2 * KVPLANE;

        float sacc[8][4];
#pragma unroll
        for (int nb = 0; nb < 8; nb++) {
#pragma unroll
            for (int jj = 0; jj < 4; jj++) sacc[nb][jj] = 0.f;
        }
#pragma unroll
        for (int nb = 0; nb < 8; nb++) {
            uint32_t kh[8], kl[8];
            uint32_t ka = kbase + (nb * 8 + (lane & 7)) * ASTRIDE + (lane >> 3) * 16;
            ldmx4(kh, ka);  ldmx4(kh + 4, ka + 64);
            ldmx4(kl, ka + KVPLANE);  ldmx4(kl + 4, ka + KVPLANE + 64);
#pragma unroll
            for (int kc = 0; kc < 4; kc++) {
                mma16816(sacc[nb], qh[kc], &kh[kc * 2]);
                mma16816(sacc[nb], qh[kc], &kl[kc * 2]);
                mma16816(sacc[nb], ql[kc], &kh[kc * 2]);
            }
        }

        if (kt >= nt - 2) {
            const int t0g = kt * 64;
#pragma unroll
            for (int nb = 0; nb < 8; nb++) {
#pragma unroll
                for (int c = 0; c < 4; c++) {
                    int tgl = t0g + nb * 8 + (lane & 3) * 2 + (c & 1);
                    int qgl = qrow_base + (c >> 1) * 8;
                    if (tgl > qgl + LCACHE) sacc[nb][c] = -1e30f;
                }
            }
        }

        uint32_t phf[4][4], plf[4][4];
#pragma unroll
        for (int i = 0; i < 2; i++) {
            float mx = -1e30f;
#pragma unroll
            for (int nb = 0; nb < 8; nb++)
                mx = fmaxf(mx, fmaxf(sacc[nb][2 * i], sacc[nb][2 * i + 1]));
            mx = fmaxf(mx, __shfl_xor_sync(0xffffffffu, mx, 1));
            mx = fmaxf(mx, __shfl_xor_sync(0xffffffffu, mx, 2));
            float mn = fmaxf(mrow[i], mx);
            float f = ex2f((mrow[i] - mn) * SCLOG2);
            mrow[i] = mn;
            float sum = 0.f;
#pragma unroll
            for (int nb = 0; nb < 8; nb++) {
                float p0 = ex2f((sacc[nb][2 * i] - mn) * SCLOG2);
                float p1 = ex2f((sacc[nb][2 * i + 1] - mn) * SCLOG2);
                sacc[nb][2 * i] = p0;
                sacc[nb][2 * i + 1] = p1;
                sum += p0 + p1;
            }
            sum += __shfl_xor_sync(0xffffffffu, sum, 1);
            sum += __shfl_xor_sync(0xffffffffu, sum, 2);
            lrow[i] = lrow[i] * f + sum;
#pragma unroll
            for (int nbd = 0; nbd < 8; nbd++) {
                oacc[nbd][2 * i] *= f;
                oacc[nbd][2 * i + 1] *= f;
            }
        }

#pragma unroll
        for (int kc = 0; kc < 4; kc++) {
#pragma unroll
            for (int q = 0; q < 4; q++) {
                int nb = 2 * kc + (q >> 1);
                float a = sacc[nb][(q & 1) * 2];
                float b = sacc[nb][(q & 1) * 2 + 1];
                __nv_bfloat16 ha, hb2;
                phf[kc][q] = pack_hi(a, b, ha, hb2);
                __nv_bfloat162 lo2 = __halves2bfloat162(
                    __float2bfloat16_rn(a - __bfloat162float(ha)),
                    __float2bfloat16_rn(b - __bfloat162float(hb2)));
                plf[kc][q] = *(uint32_t*)&lo2;
            }
        }

#pragma unroll
        for (int kc = 0; kc < 4; kc++) {
#pragma unroll
            for (int dp = 0; dp < 4; dp++) {
                uint32_t vh[4], vl[4];
                uint32_t va = vbase + (kc * 16 + ((lane >> 3) & 1) * 8 + (lane & 7)) * ASTRIDE
                            + (dp * 16 + (lane >> 4) * 8) * 2;
                ldmx4t(vh, va);
                ldmx4t(vl, va + KVPLANE);
                mma16816(oacc[dp * 2],     phf[kc], &vh[0]);
                mma16816(oacc[dp * 2],     phf[kc], &vl[0]);
                mma16816(oacc[dp * 2],     plf[kc], &vh[0]);
                mma16816(oacc[dp * 2 + 1], phf[kc], &vh[2]);
                mma16816(oacc[dp * 2 + 1], phf[kc], &vl[2]);
                mma16816(oacc[dp * 2 + 1], plf[kc], &vh[2]);
            }
        }

        cp_wait<0>();
        __syncthreads();
    }

    const int b = bh >> 4, h = bh & 15;
#pragma unroll
    for (int i = 0; i < 2; i++) {
        float inv = 1.f / lrow[i];
        int srow = q0 + w * 16 + (lane >> 2) + i * 8;
        size_t mbase = ((size_t)b * SEQ + srow) * DM + h * HD + (lane & 3) * 2;
#pragma unroll
        for (int nbd = 0; nbd < 8; nbd++) {
            float v0 = oacc[nbd][2 * i] * inv;
            float v1 = oacc[nbd][2 * i + 1] * inv;
            __nv_bfloat16 h0 = __float2bfloat16_rn(v0);
            __nv_bfloat16 h1 = __float2bfloat16_rn(v1);
            *(__nv_bfloat162*)(g_ahi + mbase + nbd * 8) = __halves2bfloat162(h0, h1);
            *(__nv_bfloat162*)(g_alo + mbase + nbd * 8) = __halves2bfloat162(
                __float2bfloat16_rn(v0 - __bfloat162float(h0)),
                __float2bfloat16_rn(v1 - __bfloat162float(h1)));
        }
    }
}

// ---------------------------------------------------------------------------
// launch
// ---------------------------------------------------------------------------
extern "C" void kernel_launch(void* const* d_in, const int* in_sizes, int n_in,
                              void* d_out, int out_size)
{
    const float* x  = (const float*)d_in[0];
    const float* ck = (const float*)d_in[1];
    const float* cv = (const float*)d_in[2];
    const float* Wq = (const float*)d_in[3];
    const float* bq = (const float*)d_in[4];
    const float* Wk = (const float*)d_in[5];
    const float* bk = (const float*)d_in[6];
    const float* Wv = (const float*)d_in[7];
    const float* bv = (const float*)d_in[8];
    const float* Wo = (const float*)d_in[9];
    const float* bo = (const float*)d_in[10];
    float* out = (float*)d_out;

    __nv_bfloat16 *xhi, *xlo, *whi, *wlo, *ahi, *alo;
    __nv_bfloat16 *qhi, *qlo, *khi, *klo, *vhi, *vlo;
    cudaGetSymbolAddress((void**)&xhi, g_xhi);
    cudaGetSymbolAddress((void**)&xlo, g_xlo);
    cudaGetSymbolAddress((void**)&whi, g_whi);
    cudaGetSymbolAddress((void**)&wlo, g_wlo);
    cudaGetSymbolAddress((void**)&ahi, g_ahi);
    cudaGetSymbolAddress((void**)&alo, g_alo);
    cudaGetSymbolAddress((void**)&qhi, g_qhi);
    cudaGetSymbolAddress((void**)&qlo, g_qlo);
    cudaGetSymbolAddress((void**)&khi, g_khi);
    cudaGetSymbolAddress((void**)&klo, g_klo);
    cudaGetSymbolAddress((void**)&vhi, g_vhi);
    cudaGetSymbolAddress((void**)&vlo, g_vlo);

    cudaFuncSetAttribute(gemm_mma, cudaFuncAttributeMaxDynamicSharedMemorySize, GSMEM);
    cudaFuncSetAttribute(attn_tc, cudaFuncAttributeMaxDynamicSharedMemorySize, ASMEM);

    // 1) fused prep: splits + cache conversion (one launch)
    prep_all<<<10240, 256>>>(x, Wq, Wk, Wv, Wo, ck, cv);

    // 2) QKV projections -> bf16 hi/lo Q/K/V planes
    gemm_mma<<<dim3(8, 16, 3), 256, GSMEM>>>(xhi, xlo, whi, wlo,
                                             bq, bk, bv,
                                             qhi, qlo, khi, klo, vhi, vlo,
                                             nullptr, 1);

    // 3) tensor-core flash attention (128-row q tiles) -> bf16 hi/lo planes
    attn_tc<<<dim3(BH, 8), 256, ASMEM>>>();

    // 4) output projection -> fp32 d_out
    gemm_mma<<<dim3(8, 16, 1), 256, GSMEM>>>(ahi, alo,
                                             whi + (size_t)3 * DM * DM, wlo + (size_t)3 * DM * DM,
                                             bo, bo, bo,
                                             nullptr, nullptr, nullptr, nullptr, nullptr, nullptr,
                                             out, 0);
}

// round 16
// speedup vs baseline: 1.7826x; 1.0140x over previous
#include <cuda_runtime.h>
#include <cuda_bf16.h>
#include <cstdint>

#define DM     1024
#define NHEADS 16
#define HD     64
#define BATCH  2
#define SEQ    1024
#define LCACHE 1024
#define TTOT   2048
#define BH     (BATCH * NHEADS)   // 32
#define MROWS  (BATCH * SEQ)      // 2048

// ---------------------------------------------------------------------------
// Scratch (device globals; no allocation allowed)
// ---------------------------------------------------------------------------
__device__ __nv_bfloat16 g_xhi[MROWS * DM], g_xlo[MROWS * DM];
__device__ __nv_bfloat16 g_whi[4 * DM * DM], g_wlo[4 * DM * DM];
__device__ __nv_bfloat16 g_qhi[BH * SEQ * HD],  g_qlo[BH * SEQ * HD];
__device__ __nv_bfloat16 g_khi[BH * TTOT * HD], g_klo[BH * TTOT * HD];
__device__ __nv_bfloat16 g_vhi[BH * TTOT * HD], g_vlo[BH * TTOT * HD];
__device__ __nv_bfloat16 g_ahi[MROWS * DM], g_alo[MROWS * DM];

// ---------------------------------------------------------------------------
// PTX helpers — baseline ISA only (compute_103-safe)
// ---------------------------------------------------------------------------
__device__ __forceinline__ uint32_t smem_u32(const void* p) {
    uint32_t a;
    asm("{ .reg .u64 t; cvta.to.shared.u64 t, %1; cvt.u32.u64 %0, t; }"
        : "=r"(a) : "l"(p));
    return a;
}
__device__ __forceinline__ void cp16(uint32_t d, const void* s) {
    asm volatile("cp.async.cg.shared.global [%0], [%1], 16;" :: "r"(d), "l"(s) : "memory");
}
__device__ __forceinline__ void cp_commit() {
    asm volatile("cp.async.commit_group;" ::: "memory");
}
template <int N> __device__ __forceinline__ void cp_wait() {
    asm volatile("cp.async.wait_group %0;" :: "n"(N) : "memory");
}
__device__ __forceinline__ void ldmx4(uint32_t* r, uint32_t a) {
    asm volatile("ldmatrix.sync.aligned.m8n8.x4.shared.b16 {%0,%1,%2,%3}, [%4];"
        : "=r"(r[0]), "=r"(r[1]), "=r"(r[2]), "=r"(r[3]) : "r"(a));
}
__device__ __forceinline__ void ldmx4t(uint32_t* r, uint32_t a) {
    asm volatile("ldmatrix.sync.aligned.m8n8.x4.trans.shared.b16 {%0,%1,%2,%3}, [%4];"
        : "=r"(r[0]), "=r"(r[1]), "=r"(r[2]), "=r"(r[3]) : "r"(a));
}
__device__ __forceinline__ void ldmx2(uint32_t* r, uint32_t a) {
    asm volatile("ldmatrix.sync.aligned.m8n8.x2.shared.b16 {%0,%1}, [%2];"
        : "=r"(r[0]), "=r"(r[1]) : "r"(a));
}
__device__ __forceinline__ void mma16816(float* d, const uint32_t* a, const uint32_t* b) {
    asm volatile(
        "mma.sync.aligned.m16n8k16.row.col.f32.bf16.bf16.f32 "
        "{%0,%1,%2,%3}, {%4,%5,%6,%7}, {%8,%9}, {%0,%1,%2,%3};"
        : "+f"(d[0]), "+f"(d[1]), "+f"(d[2]), "+f"(d[3])
        : "r"(a[0]), "r"(a[1]), "r"(a[2]), "r"(a[3]), "r"(b[0]), "r"(b[1]));
}
__device__ __forceinline__ float ex2f(float x) {
    float y;
    asm("ex2.approx.f32 %0, %1;" : "=f"(y) : "f"(x));
    return y;
}
__device__ __forceinline__ uint32_t pack_hi(float a, float b, __nv_bfloat16& ha, __nv_bfloat16& hb) {
    ha = __float2bfloat16_rn(a);
    hb = __float2bfloat16_rn(b);
    __nv_bfloat162 t = __halves2bfloat162(ha, hb);
    return *(uint32_t*)&t;
}

// ---------------------------------------------------------------------------
// split helper
// ---------------------------------------------------------------------------
__device__ __forceinline__ void split4_store(float4 v, __nv_bfloat16* hi, __nv_bfloat16* lo,
                                             size_t elem_off)
{
    __nv_bfloat16 h0 = __float2bfloat16_rn(v.x);
    __nv_bfloat16 h1 = __float2bfloat16_rn(v.y);
    __nv_bfloat16 h2 = __float2bfloat16_rn(v.z);
    __nv_bfloat16 h3 = __float2bfloat16_rn(v.w);
    __nv_bfloat16 l0 = __float2bfloat16_rn(v.x - __bfloat162float(h0));
    __nv_bfloat16 l1 = __float2bfloat16_rn(v.y - __bfloat162float(h1));
    __nv_bfloat16 l2 = __float2bfloat16_rn(v.z - __bfloat162float(h2));
    __nv_bfloat16 l3 = __float2bfloat16_rn(v.w - __bfloat162float(h3));
    *(__nv_bfloat162*)(hi + elem_off)     = __halves2bfloat162(h0, h1);
    *(__nv_bfloat162*)(hi + elem_off + 2) = __halves2bfloat162(h2, h3);
    *(__nv_bfloat162*)(lo + elem_off)     = __halves2bfloat162(l0, l1);
    *(__nv_bfloat162*)(lo + elem_off + 2) = __halves2bfloat162(l2, l3);
}

// ---------------------------------------------------------------------------
// prep: split x + 4 weights only (KV conversion rides inside the QKV launch)
// 6144 blocks x 256 threads, one float4 each.
// ---------------------------------------------------------------------------
__global__ void prep_all(const float* __restrict__ x,
                         const float* __restrict__ w0, const float* __restrict__ w1,
                         const float* __restrict__ w2, const float* __restrict__ w3)
{
    const int b = blockIdx.x;
    const int tid = threadIdx.x;
    if (b < 2048) {
        int i = b * 256 + tid;
        split4_store(((const float4*)x)[i], g_xhi, g_xlo, (size_t)i * 4);
    } else {
        int p = (b - 2048) >> 10;
        int i = ((b - 2048) & 1023) * 256 + tid;
        const float* src = (p == 0) ? w0 : (p == 1) ? w1 : (p == 2) ? w2 : w3;
        size_t off = (size_t)p * (DM * DM) + (size_t)i * 4;
        split4_store(((const float4*)src)[i], g_whi, g_wlo, off);
    }
}

// ---------------------------------------------------------------------------
// Warp-MMA bf16 GEMM (hi/lo 3-term) — R12 config, ONE barrier per chunk.
// grid.z==3 CTAs instead run the fp32 KV-cache -> bf16 hi/lo conversion,
// filling QKV's partial third wave and idle DRAM.
// ---------------------------------------------------------------------------
#define ST       3
#define CHUNKS   32
#define ROWPAD   80
#define PLANE_B  (128 * ROWPAD)
#define STAGE_B  (4 * PLANE_B)
#define GSMEM    (ST * STAGE_B)

__global__ __launch_bounds__(256, 1)
void gemm_mma(const __nv_bfloat16* __restrict__ Ahi, const __nv_bfloat16* __restrict__ Alo,
              const __nv_bfloat16* __restrict__ Whi, const __nv_bfloat16* __restrict__ Wlo,
              const float* __restrict__ b0, const float* __restrict__ b1, const float* __restrict__ b2,
              __nv_bfloat16* __restrict__ ph0, __nv_bfloat16* __restrict__ pl0,
              __nv_bfloat16* __restrict__ ph1, __nv_bfloat16* __restrict__ pl1,
              __nv_bfloat16* __restrict__ ph2, __nv_bfloat16* __restrict__ pl2,
              float* __restrict__ fout,
              const float* __restrict__ ck, const float* __restrict__ cv,
              int headwise)
{
    const int z = blockIdx.z;

    if (z == 3) {
        // KV-cache conversion: 128 CTAs x 256 thr x 32 float4 each.
        // float4 index space: [0, 1048576): first half ck, second half cv.
        const int cta = blockIdx.y * 8 + blockIdx.x;      // 0..127
        int base = cta * 8192 + threadIdx.x;
        #pragma unroll 4
        for (int it = 0; it < 32; it++) {
            int idx = base + it * 256;
            int which = idx >= 524288;
            int i = idx - (which ? 524288 : 0);
            const float* src = which ? cv : ck;
            __nv_bfloat16* hi = which ? g_vhi : g_khi;
            __nv_bfloat16* lo = which ? g_vlo : g_klo;
            int el = i * 4;
            int bh = el >> 16;              // LCACHE*HD = 65536
            int rest = el & 65535;
            size_t o = (size_t)bh * (TTOT * HD) + rest;
            split4_store(((const float4*)src)[i], hi, lo, o);
        }
        return;
    }

    extern __shared__ char smem[];
    const uint32_t sb = smem_u32(smem);
    const int tid = threadIdx.x, wid = tid >> 5, lane = tid & 31;
    const int n0 = blockIdx.x * 128, m0 = blockIdx.y * 128;
    const __nv_bfloat16* Wh = Whi + (size_t)z * DM * DM;
    const __nv_bfloat16* Wl = Wlo + (size_t)z * DM * DM;
    const float* bias = (z == 0) ? b0 : (z == 1) ? b1 : b2;

    const int wm = wid & 1;
    const int wn = wid >> 1;

    auto load_chunk = [&](int stage, int koff) {
        const uint32_t base = sb + stage * STAGE_B;
#pragma unroll
        for (int it = 0; it < 8; it++) {
            int g = it * 256 + tid;
            int plane = g >> 9;
            int row = (g >> 2) & 127;
            int c = g & 3;
            uint32_t dst = base + plane * PLANE_B + row * ROWPAD + c * 16;
            const __nv_bfloat16* src;
            if (plane == 0)      src = Ahi + (size_t)(m0 + row) * DM + koff + c * 8;
            else if (plane == 1) src = Alo + (size_t)(m0 + row) * DM + koff + c * 8;
            else if (plane == 2) src = Wh  + (size_t)(n0 + row) * DM + koff + c * 8;
            else                 src = Wl  + (size_t)(n0 + row) * DM + koff + c * 8;
            cp16(dst, src);
        }
        cp_commit();
    };

    load_chunk(0, 0);
    load_chunk(1, 32);

    float acc[4][4][4];
#pragma unroll
    for (int i = 0; i < 4; i++)
#pragma unroll
        for (int j = 0; j < 4; j++)
#pragma unroll
            for (int r = 0; r < 4; r++) acc[i][j][r] = 0.f;

    const int lr16 = lane & 15, lc16 = lane >> 4;
    const int br8 = lane & 7, bc8 = (lane >> 3) & 1;

    for (int i = 0; i < CHUNKS; i++) {
        cp_wait<1>();
        __syncthreads();

        const uint32_t stb = sb + (i % ST) * STAGE_B;
#pragma unroll
        for (int ks = 0; ks < 2; ks++) {
            uint32_t ah[4][4], al[4][4];
#pragma unroll
            for (int mi = 0; mi < 4; mi++) {
                uint32_t ad = stb + (wm * 64 + mi * 16 + lr16) * ROWPAD + ks * 32 + lc16 * 16;
                ldmx4(ah[mi], ad);
                ldmx4(al[mi], ad + PLANE_B);
            }
            uint32_t bh[4][2], bl[4][2];
#pragma unroll
            for (int nj = 0; nj < 4; nj++) {
                uint32_t bd = stb + 2 * PLANE_B + (wn * 32 + nj * 8 + br8) * ROWPAD + ks * 32 + bc8 * 16;
                ldmx2(bh[nj], bd);
                ldmx2(bl[nj], bd + PLANE_B);
            }
#pragma unroll
            for (int mi = 0; mi < 4; mi++)
#pragma unroll
                for (int nj = 0; nj < 4; nj++) {
                    mma16816(acc[mi][nj], ah[mi], bh[nj]);
                    mma16816(acc[mi][nj], ah[mi], bl[nj]);
                    mma16816(acc[mi][nj], al[mi], bh[nj]);
                }
        }

        if (i + 2 < CHUNKS) load_chunk((i + 2) % ST, (i + 2) * 32);
        else cp_commit();   // keep per-thread group counts uniform for cp_wait<1>
    }

    // epilogue
    __nv_bfloat16* ph = (z == 0) ? ph0 : (z == 1) ? ph1 : ph2;
    __nv_bfloat16* pl = (z == 0) ? pl0 : (z == 1) ? pl1 : pl2;
    const int tstr = (z == 0) ? SEQ : TTOT;
    const int toff = (z == 0) ? 0 : LCACHE;

#pragma unroll
    for (int nj = 0; nj < 4; nj++) {
        const int n = n0 + wn * 32 + nj * 8 + (lane & 3) * 2;
        const float bx = bias[n], by = bias[n + 1];
        const int h = n >> 6, d = n & 63;
#pragma unroll
        for (int mi = 0; mi < 4; mi++) {
#pragma unroll
            for (int half = 0; half < 2; half++) {
                const int m = m0 + wm * 64 + mi * 16 + (lane >> 2) + half * 8;
                float vx = acc[mi][nj][half * 2] + bx;
                float vy = acc[mi][nj][half * 2 + 1] + by;
                if (headwise) {
                    int b = m >> 10, s = m & 1023;
                    size_t ad = (((size_t)b * NHEADS + h) * tstr + toff + s) * HD + d;
                    __nv_bfloat16 hx = __float2bfloat16_rn(vx);
                    __nv_bfloat16 hy = __float2bfloat16_rn(vy);
                    *(__nv_bfloat162*)(ph + ad) = __halves2bfloat162(hx, hy);
                    *(__nv_bfloat162*)(pl + ad) = __halves2bfloat162(
                        __float2bfloat16_rn(vx - __bfloat162float(hx)),
                        __float2bfloat16_rn(vy - __bfloat162float(hy)));
                } else {
                    *(float2*)&fout[(size_t)m * DM + n] = make_float2(vx, vy);
                }
            }
        }
    }
}

// ---------------------------------------------------------------------------
// Tensor-core flash attention, 128-row q tiles. Wait hoisted to point of use:
// per iter: [wait(load kt) if kt>0; barrier; issue load(kt+1); compute(kt)].
// ---------------------------------------------------------------------------
#define ASTRIDE  144
#define QPLANE   (128 * ASTRIDE)
#define KVPLANE  (64 * ASTRIDE)
#define AKVOFF   (2 * QPLANE)
#define KVSTAGE  (4 * KVPLANE)
#define ASMEM    (2 * QPLANE + 2 * KVSTAGE)
#define SCLOG2   0.18033688011112042f

__global__ __launch_bounds__(256, 1)
void attn_tc()
{
    extern __shared__ char smem[];
    const uint32_t sb = smem_u32(smem);
    const int tid = threadIdx.x, w = tid >> 5, lane = tid & 31;
    const int bh = blockIdx.x;
    const int j = 7 - blockIdx.y;
    const int q0 = j * 128;
    const int nt = 2 * j + 18;

#pragma unroll
    for (int it = 0; it < 8; it++) {
        int g = it * 256 + tid;
        int plane = g >> 10, row = (g >> 3) & 127, gc = g & 7;
        const __nv_bfloat16* src = (plane ? g_qlo : g_qhi)
            + ((size_t)bh * SEQ + q0 + row) * HD + gc * 8;
        cp16(sb + plane * QPLANE + row * ASTRIDE + gc * 16, src);
    }
    cp_commit();

    auto load_kv = [&](int kt, int st) {
        uint32_t base = sb + AKVOFF + st * KVSTAGE;
        int t0 = kt * 64;
#pragma unroll
        for (int it = 0; it < 8; it++) {
            int g = it * 256 + tid;
            int plane = g >> 9, row = (g >> 3) & 63, gc = g & 7;
            size_t off = ((size_t)bh * TTOT + t0 + row) * HD + gc * 8;
            const __nv_bfloat16* src;
            if (plane == 0)      src = g_khi + off;
            else if (plane == 1) src = g_klo + off;
            else if (plane == 2) src = g_vhi + off;
            else                 src = g_vlo + off;
            cp16(base + plane * KVPLANE + row * ASTRIDE + gc * 16, src);
        }
        cp_commit();
    };
    load_kv(0, 0);
    cp_wait<0>();
    __syncthreads();

    uint32_t qh[4][4], ql[4][4];
#pragma unroll
    for (int kc = 0; kc < 4; kc++) {
        uint32_t qa = sb + (w * 16 + (lane & 15)) * ASTRIDE + kc * 32 + (lane >> 4) * 16;
        ldmx4(qh[kc], qa);
        ldmx4(ql[kc], qa + QPLANE);
    }

    float oacc[8][4];
#pragma unroll
    for (int i = 0; i < 8; i++)
#pragma unroll
        for (int jj = 0; jj < 4; jj++) oacc[i][jj] = 0.f;
    float mrow[2] = {-1e30f, -1e30f}, lrow[2] = {0.f, 0.f};

    const int qrow_base = q0 + w * 16 + (lane >> 2);

    for (int kt = 0; kt < nt; kt++) {
        const int st = kt & 1;
        if (kt > 0) {
            cp_wait<0>();        // load(kt) arrived
            __syncthreads();     // all warps done reading stage st (iter kt-1 writes st^1 reuse)
        }
        if (kt + 1 < nt) load_kv(kt + 1, st ^ 1);

        const uint32_t kbase = sb + AKVOFF + st * KVSTAGE;
        const uint32_t vbase = kbase + 2 * KVPLANE;

        float sacc[8][4];
#pragma unroll
        for (int nb = 0; nb < 8; nb++) {
#pragma unroll
            for (int jj = 0; jj < 4; jj++) sacc[nb][jj] = 0.f;
        }
#pragma unroll
        for (int nb = 0; nb < 8; nb++) {
            uint32_t kh[8], kl[8];
            uint32_t ka = kbase + (nb * 8 + (lane & 7)) * ASTRIDE + (lane >> 3) * 16;
            ldmx4(kh, ka);  ldmx4(kh + 4, ka + 64);
            ldmx4(kl, ka + KVPLANE);  ldmx4(kl + 4, ka + KVPLANE + 64);
#pragma unroll
            for (int kc = 0; kc < 4; kc++) {
                mma16816(sacc[nb], qh[kc], &kh[kc * 2]);
                mma16816(sacc[nb], qh[kc], &kl[kc * 2]);
                mma16816(sacc[nb], ql[kc], &kh[kc * 2]);
            }
        }

        if (kt >= nt - 2) {
            const int t0g = kt * 64;
#pragma unroll
            for (int nb = 0; nb < 8; nb++) {
#pragma unroll
                for (int c = 0; c < 4; c++) {
                    int tgl = t0g + nb * 8 + (lane & 3) * 2 + (c & 1);
                    int qgl = qrow_base + (c >> 1) * 8;
                    if (tgl > qgl + LCACHE) sacc[nb][c] = -1e30f;
                }
            }
        }

        uint32_t phf[4][4], plf[4][4];
#pragma unroll
        for (int i = 0; i < 2; i++) {
            float mx = -1e30f;
#pragma unroll
            for (int nb = 0; nb < 8; nb++)
                mx = fmaxf(mx, fmaxf(sacc[nb][2 * i], sacc[nb][2 * i + 1]));
            mx = fmaxf(mx, __shfl_xor_sync(0xffffffffu, mx, 1));
            mx = fmaxf(mx, __shfl_xor_sync(0xffffffffu, mx, 2));
            float mn = fmaxf(mrow[i], mx);
            float f = ex2f((mrow[i] - mn) * SCLOG2);
            mrow[i] = mn;
            float sum = 0.f;
#pragma unroll
            for (int nb = 0; nb < 8; nb++) {
                float p0 = ex2f((sacc[nb][2 * i] - mn) * SCLOG2);
                float p1 = ex2f((sacc[nb][2 * i + 1] - mn) * SCLOG2);
                sacc[nb][2 * i] = p0;
                sacc[nb][2 * i + 1] = p1;
                sum += p0 + p1;
            }
            sum += __shfl_xor_sync(0xffffffffu, sum, 1);
            sum += __shfl_xor_sync(0xffffffffu, sum, 2);
            lrow[i] = lrow[i] * f + sum;
#pragma unroll
            for (int nbd = 0; nbd < 8; nbd++) {
                oacc[nbd][2 * i] *= f;
                oacc[nbd][2 * i + 1] *= f;
            }
        }

#pragma unroll
        for (int kc = 0; kc < 4; kc++) {
#pragma unroll
            for (int q = 0; q < 4; q++) {
                int nb = 2 * kc + (q >> 1);
                float a = sacc[nb][(q & 1) * 2];
                float b = sacc[nb][(q & 1) * 2 + 1];
                __nv_bfloat16 ha, hb2;
                phf[kc][q] = pack_hi(a, b, ha, hb2);
                __nv_bfloat162 lo2 = __halves2bfloat162(
                    __float2bfloat16_rn(a - __bfloat162float(ha)),
                    __float2bfloat16_rn(b - __bfloat162float(hb2)));
                plf[kc][q] = *(uint32_t*)&lo2;
            }
        }

#pragma unroll
        for (int kc = 0; kc < 4; kc++) {
#pragma unroll
            for (int dp = 0; dp < 4; dp++) {
                uint32_t vh[4], vl[4];
                uint32_t va = vbase + (kc * 16 + ((lane >> 3) & 1) * 8 + (lane & 7)) * ASTRIDE
                            + (dp * 16 + (lane >> 4) * 8) * 2;
                ldmx4t(vh, va);
                ldmx4t(vl, va + KVPLANE);
                mma16816(oacc[dp * 2],     phf[kc], &vh[0]);
                mma16816(oacc[dp * 2],     phf[kc], &vl[0]);
                mma16816(oacc[dp * 2],     plf[kc], &vh[0]);
                mma16816(oacc[dp * 2 + 1], phf[kc], &vh[2]);
                mma16816(oacc[dp * 2 + 1], phf[kc], &vl[2]);
                mma16816(oacc[dp * 2 + 1], plf[kc], &vh[2]);
            }
        }
    }

    const int b = bh >> 4, h = bh & 15;
#pragma unroll
    for (int i = 0; i < 2; i++) {
        float inv = 1.f / lrow[i];
        int srow = q0 + w * 16 + (lane >> 2) + i * 8;
        size_t mbase = ((size_t)b * SEQ + srow) * DM + h * HD + (lane & 3) * 2;
#pragma unroll
        for (int nbd = 0; nbd < 8; nbd++) {
            float v0 = oacc[nbd][2 * i] * inv;
            float v1 = oacc[nbd][2 * i + 1] * inv;
            __nv_bfloat16 h0 = __float2bfloat16_rn(v0);
            __nv_bfloat16 h1 = __float2bfloat16_rn(v1);
            *(__nv_bfloat162*)(g_ahi + mbase + nbd * 8) = __halves2bfloat162(h0, h1);
            *(__nv_bfloat162*)(g_alo + mbase + nbd * 8) = __halves2bfloat162(
                __float2bfloat16_rn(v0 - __bfloat162float(h0)),
                __float2bfloat16_rn(v1 - __bfloat162float(h1)));
        }
    }
}

// ---------------------------------------------------------------------------
// launch
// ---------------------------------------------------------------------------
extern "C" void kernel_launch(void* const* d_in, const int* in_sizes, int n_in,
                              void* d_out, int out_size)
{
    const float* x  = (const float*)d_in[0];
    const float* ck = (const float*)d_in[1];
    const float* cv = (const float*)d_in[2];
    const float* Wq = (const float*)d_in[3];
    const float* bq = (const float*)d_in[4];
    const float* Wk = (const float*)d_in[5];
    const float* bk = (const float*)d_in[6];
    const float* Wv = (const float*)d_in[7];
    const float* bv = (const float*)d_in[8];
    const float* Wo = (const float*)d_in[9];
    const float* bo = (const float*)d_in[10];
    float* out = (float*)d_out;

    __nv_bfloat16 *xhi, *xlo, *whi, *wlo, *ahi, *alo;
    __nv_bfloat16 *qhi, *qlo, *khi, *klo, *vhi, *vlo;
    cudaGetSymbolAddress((void**)&xhi, g_xhi);
    cudaGetSymbolAddress((void**)&xlo, g_xlo);
    cudaGetSymbolAddress((void**)&whi, g_whi);
    cudaGetSymbolAddress((void**)&wlo, g_wlo);
    cudaGetSymbolAddress((void**)&ahi, g_ahi);
    cudaGetSymbolAddress((void**)&alo, g_alo);
    cudaGetSymbolAddress((void**)&qhi, g_qhi);
    cudaGetSymbolAddress((void**)&qlo, g_qlo);
    cudaGetSymbolAddress((void**)&khi, g_khi);
    cudaGetSymbolAddress((void**)&klo, g_klo);
    cudaGetSymbolAddress((void**)&vhi, g_vhi);
    cudaGetSymbolAddress((void**)&vlo, g_vlo);

    cudaFuncSetAttribute(gemm_mma, cudaFuncAttributeMaxDynamicSharedMemorySize, GSMEM);
    cudaFuncSetAttribute(attn_tc, cudaFuncAttributeMaxDynamicSharedMemorySize, ASMEM);

    // 1) prep: split x + weights (KV conversion rides inside the QKV launch)
    prep_all<<<6144, 256>>>(x, Wq, Wk, Wv, Wo);

    // 2) QKV projections (z=0..2) + KV-cache conversion (z=3)
    gemm_mma<<<dim3(8, 16, 4), 256, GSMEM>>>(xhi, xlo, whi, wlo,
                                             bq, bk, bv,
                                             qhi, qlo, khi, klo, vhi, vlo,
                                             nullptr, ck, cv, 1);

    // 3) tensor-core flash attention (128-row q tiles) -> bf16 hi/lo planes
    attn_tc<<<dim3(BH, 8), 256, ASMEM>>>();

    // 4) output projection -> fp32 d_out
    gemm_mma<<<dim3(8, 16, 1), 256, GSMEM>>>(ahi, alo,
                                             whi + (size_t)3 * DM * DM, wlo + (size_t)3 * DM * DM,
                                             bo, bo, bo,
                                             nullptr, nullptr, nullptr, nullptr, nullptr, nullptr,
                                             out, nullptr, nullptr, 0);
}